// round 2
// baseline (speedup 1.0000x reference)
#include <cuda_runtime.h>
#include <cuda_bf16.h>

// ---------------- Problem constants ----------------
#define BATCH 64
#define NPATCH 196          // 14*14
#define D 768
#define T 8
#define HMETA 192
#define ROWS_TOT (BATCH * NPATCH)   // 12544
#define DD (D * D)                   // 589824

// ---------------- Device scratch ----------------
__device__ float g_patches[(size_t)ROWS_TOT * D];   // 38.5 MB
__device__ float g_h[(size_t)ROWS_TOT * D];         // 38.5 MB
__device__ float g_pooled[BATCH * D];
__device__ float g_pooled2[BATCH * D];
__device__ float g_base[BATCH * D];
__device__ float g_hid[BATCH * HMETA];
__device__ float g_coefs[BATCH * T];
__device__ float g_nb1[BATCH * D];
__device__ float g_nb2[BATCH * D];
__device__ float g_mixW1[(size_t)BATCH * DD];       // 151 MB
__device__ float g_q[BATCH * T * D];

// ---------------- patchify ----------------
// patches[b, n, d] = x[b, c, hp*16+i, wp*16+j]
// n = hp*14+wp ; d = c*256 + i*16 + j
__global__ void patchify_kernel(const float* __restrict__ x, float* __restrict__ out)
{
    int idx = blockIdx.x * blockDim.x + threadIdx.x;
    const int total = ROWS_TOT * D;
    if (idx >= total) return;
    int d = idx % D;
    int rem = idx / D;
    int n = rem % NPATCH;
    int b = rem / NPATCH;
    int c = d >> 8;            // /256
    int r2 = d & 255;
    int i = r2 >> 4;
    int j = r2 & 15;
    int hp = n / 14;
    int wp = n % 14;
    int src = ((b * 3 + c) * 224 + hp * 16 + i) * 224 + wp * 16 + j;
    out[idx] = x[src];
}

// ---------------- Generic tiled SGEMM ----------------
// C[batch] = (relu?)(A[batch] @ B[batch] + bias[batch]) ; row-major with ld's.
#define BM 128
#define BN 128
#define BKK 8
#define TM 8
#define TN 8

__global__ __launch_bounds__(256, 2)
void sgemm_kernel(const float* __restrict__ A, const float* __restrict__ B,
                  const float* __restrict__ bias, float* __restrict__ C,
                  int M, int N, int K, int ldA, int ldB, int ldC,
                  long long sA, long long sB, long long sBias, long long sC,
                  int relu)
{
    long long batch = blockIdx.z;
    A += batch * sA;
    B += batch * sB;
    C += batch * sC;
    if (bias) bias += batch * sBias;

    __shared__ float As[BKK][BM];
    __shared__ float Bs[BKK][BN];

    int tid = threadIdx.x;
    int tx = tid & 15;
    int ty = tid >> 4;
    int rowBase = blockIdx.y * BM;
    int colBase = blockIdx.x * BN;

    float acc[TM][TN];
#pragma unroll
    for (int i = 0; i < TM; i++)
#pragma unroll
        for (int j = 0; j < TN; j++) acc[i][j] = 0.f;

    int aRow = tid >> 1;            // 0..127
    int aK   = (tid & 1) * 4;       // 0 or 4
    int bK   = tid >> 5;            // 0..7
    int bCol = (tid & 31) * 4;      // 0..124

    for (int k0 = 0; k0 < K; k0 += BKK) {
        // ---- load A tile (BMxBK), store transposed ----
        {
            int gRow = rowBase + aRow;
            float4 av = make_float4(0.f, 0.f, 0.f, 0.f);
            if (gRow < M) {
                const float* ap = A + (long long)gRow * ldA + k0 + aK;
                av = *reinterpret_cast<const float4*>(ap);   // K % 8 == 0 always
            }
            As[aK + 0][aRow] = av.x;
            As[aK + 1][aRow] = av.y;
            As[aK + 2][aRow] = av.z;
            As[aK + 3][aRow] = av.w;
        }
        // ---- load B tile (BKxBN) ----
        {
            int gCol = colBase + bCol;
            float4 bv = make_float4(0.f, 0.f, 0.f, 0.f);
            int gk = k0 + bK;       // always < K (K % 8 == 0)
            if (gCol + 3 < N) {
                bv = *reinterpret_cast<const float4*>(B + (long long)gk * ldB + gCol);
            } else if (gCol < N) {
                const float* bp = B + (long long)gk * ldB;
                float tmp[4] = {0.f, 0.f, 0.f, 0.f};
                for (int u = 0; u < 4; u++)
                    if (gCol + u < N) tmp[u] = bp[gCol + u];
                bv = make_float4(tmp[0], tmp[1], tmp[2], tmp[3]);
            }
            *reinterpret_cast<float4*>(&Bs[bK][bCol]) = bv;
        }
        __syncthreads();

#pragma unroll
        for (int k = 0; k < BKK; k++) {
            float ra[TM], rb[TN];
            *reinterpret_cast<float4*>(&ra[0]) = *reinterpret_cast<float4*>(&As[k][ty * 8]);
            *reinterpret_cast<float4*>(&ra[4]) = *reinterpret_cast<float4*>(&As[k][ty * 8 + 4]);
            *reinterpret_cast<float4*>(&rb[0]) = *reinterpret_cast<float4*>(&Bs[k][tx * 8]);
            *reinterpret_cast<float4*>(&rb[4]) = *reinterpret_cast<float4*>(&Bs[k][tx * 8 + 4]);
#pragma unroll
            for (int i = 0; i < TM; i++)
#pragma unroll
                for (int j = 0; j < TN; j++)
                    acc[i][j] = fmaf(ra[i], rb[j], acc[i][j]);
        }
        __syncthreads();
    }

    // ---- epilogue ----
#pragma unroll
    for (int i = 0; i < TM; i++) {
        int r = rowBase + ty * 8 + i;
        if (r >= M) continue;
#pragma unroll
        for (int j = 0; j < TN; j++) {
            int cidx = colBase + tx * 8 + j;
            if (cidx >= N) continue;
            float v = acc[i][j];
            if (bias) v += bias[cidx];
            if (relu) v = fmaxf(v, 0.f);
            C[(long long)r * ldC + cidx] = v;
        }
    }
}

// ---------------- mean pool over patches ----------------
__global__ void pool_kernel(const float* __restrict__ h, float* __restrict__ pooled)
{
    int idx = blockIdx.x * blockDim.x + threadIdx.x;
    if (idx >= BATCH * D) return;
    int d = idx % D;
    int b = idx / D;
    const float* p = h + ((long long)b * NPATCH) * D + d;
    float s = 0.f;
#pragma unroll 4
    for (int n = 0; n < NPATCH; n++) s += p[(long long)n * D];
    pooled[idx] = s * (1.0f / NPATCH);
}

// ---------------- mixed biases nb1, nb2 ----------------
__global__ void mixbias_kernel(const float* __restrict__ b1, const float* __restrict__ db1,
                               const float* __restrict__ b2, const float* __restrict__ db2,
                               float* __restrict__ nb1, float* __restrict__ nb2)
{
    int idx = blockIdx.x * blockDim.x + threadIdx.x;
    if (idx >= BATCH * D) return;
    int j = idx % D;
    int b = idx / D;
    float c[T];
#pragma unroll
    for (int t = 0; t < T; t++) c[t] = g_coefs[b * T + t];
    float v1 = b1[j], v2 = b2[j];
#pragma unroll
    for (int t = 0; t < T; t++) {
        v1 = fmaf(c[t], db1[t * D + j], v1);
        v2 = fmaf(c[t], db2[t * D + j], v2);
    }
    nb1[idx] = v1;
    nb2[idx] = v2;
}

// ---------------- mixed W1: mixW1[b] = W1 + sum_t c[b,t] dW1[t] ----------------
__global__ void mixw1_kernel(const float* __restrict__ W1, const float* __restrict__ dW1)
{
    long long idx4 = (long long)blockIdx.x * blockDim.x + threadIdx.x;
    const long long per_b4 = DD / 4;                 // 147456
    const long long total4 = (long long)BATCH * per_b4;
    if (idx4 >= total4) return;
    long long b = idx4 / per_b4;
    long long r = idx4 - b * per_b4;

    float c[T];
#pragma unroll
    for (int t = 0; t < T; t++) c[t] = g_coefs[b * T + t];

    float4 v = reinterpret_cast<const float4*>(W1)[r];
#pragma unroll
    for (int t = 0; t < T; t++) {
        float4 dv = reinterpret_cast<const float4*>(dW1)[(long long)t * per_b4 + r];
        v.x = fmaf(c[t], dv.x, v.x);
        v.y = fmaf(c[t], dv.y, v.y);
        v.z = fmaf(c[t], dv.z, v.z);
        v.w = fmaf(c[t], dv.w, v.w);
    }
    reinterpret_cast<float4*>(g_mixW1)[b * per_b4 + r] = v;
}

// ---------------- final epilogue: out += nb2 + sum_t c[b,t]*q[b,t,:] ----------------
__global__ void out_epilogue_kernel(float* __restrict__ out)
{
    int idx = blockIdx.x * blockDim.x + threadIdx.x;
    if (idx >= BATCH * D) return;
    int e = idx % D;
    int b = idx / D;
    float v = out[idx] + g_nb2[idx];
#pragma unroll
    for (int t = 0; t < T; t++)
        v = fmaf(g_coefs[b * T + t], g_q[(b * T + t) * D + e], v);
    out[idx] = v;
}

// ---------------- launch ----------------
static inline dim3 gemm_grid(int M, int N, int batch)
{
    return dim3((N + BN - 1) / BN, (M + BM - 1) / BM, batch);
}

extern "C" void kernel_launch(void* const* d_in, const int* in_sizes, int n_in,
                              void* d_out, int out_size)
{
    const float* x   = (const float*)d_in[0];
    const float* W1  = (const float*)d_in[1];
    const float* b1  = (const float*)d_in[2];
    const float* W2  = (const float*)d_in[3];
    const float* b2  = (const float*)d_in[4];
    const float* dW1 = (const float*)d_in[5];
    const float* db1 = (const float*)d_in[6];
    const float* dW2 = (const float*)d_in[7];
    const float* db2 = (const float*)d_in[8];
    const float* mw1 = (const float*)d_in[9];
    const float* mb1 = (const float*)d_in[10];
    const float* mw2 = (const float*)d_in[11];
    const float* mb2 = (const float*)d_in[12];
    float* out = (float*)d_out;

    float *patches, *h, *pooled, *pooled2, *base, *hid, *coefs, *nb1, *nb2, *mixW1, *q;
    cudaGetSymbolAddress((void**)&patches, g_patches);
    cudaGetSymbolAddress((void**)&h,       g_h);
    cudaGetSymbolAddress((void**)&pooled,  g_pooled);
    cudaGetSymbolAddress((void**)&pooled2, g_pooled2);
    cudaGetSymbolAddress((void**)&base,    g_base);
    cudaGetSymbolAddress((void**)&hid,     g_hid);
    cudaGetSymbolAddress((void**)&coefs,   g_coefs);
    cudaGetSymbolAddress((void**)&nb1,     g_nb1);
    cudaGetSymbolAddress((void**)&nb2,     g_nb2);
    cudaGetSymbolAddress((void**)&mixW1,   g_mixW1);
    cudaGetSymbolAddress((void**)&q,       g_q);

    const int TPB = 256;

    // 1) patchify
    {
        int total = ROWS_TOT * D;
        patchify_kernel<<<(total + TPB - 1) / TPB, TPB>>>(x, patches);
    }

    // 2) h = relu(patches @ W1 + b1)
    sgemm_kernel<<<gemm_grid(ROWS_TOT, D, 1), 256>>>(
        patches, W1, b1, h, ROWS_TOT, D, D, D, D, D, 0, 0, 0, 0, 1);

    // 3) pooled = mean_n h
    pool_kernel<<<(BATCH * D + TPB - 1) / TPB, TPB>>>(h, pooled);

    // 4) base = pooled @ W2 + b2
    sgemm_kernel<<<gemm_grid(BATCH, D, 1), 256>>>(
        pooled, W2, b2, base, BATCH, D, D, D, D, D, 0, 0, 0, 0, 0);

    // 5) hid = relu(base @ mw1 + mb1)
    sgemm_kernel<<<gemm_grid(BATCH, HMETA, 1), 256>>>(
        base, mw1, mb1, hid, BATCH, HMETA, D, D, HMETA, HMETA, 0, 0, 0, 0, 1);

    // 6) coefs = hid @ mw2 + mb2
    sgemm_kernel<<<gemm_grid(BATCH, T, 1), 256>>>(
        hid, mw2, mb2, coefs, BATCH, T, HMETA, HMETA, T, T, 0, 0, 0, 0, 0);

    // 7) nb1/nb2 mixed biases
    mixbias_kernel<<<(BATCH * D + TPB - 1) / TPB, TPB>>>(b1, db1, b2, db2, nb1, nb2);

    // 8) mixW1[b] = W1 + sum_t c dW1[t]
    {
        long long total4 = (long long)BATCH * (DD / 4);
        mixw1_kernel<<<(unsigned)((total4 + TPB - 1) / TPB), TPB>>>(W1, dW1);
    }

    // 9) h = relu(patches @ mixW1[b] + nb1[b])   (batched over b)
    sgemm_kernel<<<gemm_grid(NPATCH, D, BATCH), 256>>>(
        patches, mixW1, nb1, h,
        NPATCH, D, D, D, D, D,
        (long long)NPATCH * D, (long long)DD, (long long)D, (long long)NPATCH * D, 1);

    // 10) pooled2 = mean_n h
    pool_kernel<<<(BATCH * D + TPB - 1) / TPB, TPB>>>(h, pooled2);

    // 11) q[b,t,:] = pooled2[b] @ dW2[t]   (batched over t, A shared)
    sgemm_kernel<<<gemm_grid(BATCH, D, T), 256>>>(
        pooled2, dW2, nullptr, q,
        BATCH, D, D, D, D, T * D,
        0, (long long)DD, 0, (long long)D, 0);

    // 12) out = pooled2 @ W2
    sgemm_kernel<<<gemm_grid(BATCH, D, 1), 256>>>(
        pooled2, W2, nullptr, out, BATCH, D, D, D, D, D, 0, 0, 0, 0, 0);

    // 13) out += nb2 + sum_t c*q
    out_epilogue_kernel<<<(BATCH * D + TPB - 1) / TPB, TPB>>>(out);
}

// round 3
// speedup vs baseline: 2.0649x; 2.0649x over previous
#include <cuda_runtime.h>
#include <cuda_bf16.h>
#include <cstdint>

// ---------------- Problem constants ----------------
#define BATCH 64
#define NPATCH 196          // 14*14
#define D 768
#define T 8
#define HMETA 192
#define ROWS_TOT (BATCH * NPATCH)   // 12544
#define DD (D * D)                   // 589824
#define SPLITS 6                     // K splits for small gemms (768/6 = 128)

// ---------------- Device scratch ----------------
__device__ float g_patches[(size_t)ROWS_TOT * D];   // 38.5 MB
__device__ float g_h[(size_t)ROWS_TOT * D];         // 38.5 MB
__device__ float g_pooled[BATCH * D];
__device__ float g_pooled2[BATCH * D];
__device__ float g_base[BATCH * D];
__device__ float g_hid[BATCH * HMETA];
__device__ float g_coefs[BATCH * T];
__device__ float g_nb1[BATCH * D];
__device__ float g_nb2[BATCH * D];
__device__ float g_mixW1[(size_t)BATCH * DD];       // 151 MB
__device__ float g_part[(size_t)(T + 1) * SPLITS * BATCH * D];  // 10.6 MB

// ---------------- f32x2 helpers ----------------
__device__ __forceinline__ unsigned long long pk2(float x) {
    unsigned long long r;
    asm("mov.b64 %0, {%1, %1};" : "=l"(r) : "f"(x));
    return r;
}
__device__ __forceinline__ unsigned long long ffma2(unsigned long long a,
                                                    unsigned long long b,
                                                    unsigned long long c) {
    unsigned long long d;
    asm("fma.rn.f32x2 %0, %1, %2, %3;" : "=l"(d) : "l"(a), "l"(b), "l"(c));
    return d;
}
__device__ __forceinline__ void upk2(unsigned long long v, float& lo, float& hi) {
    asm("mov.b64 {%0, %1}, %2;" : "=f"(lo), "=f"(hi) : "l"(v));
}
__device__ __forceinline__ void cpasync16(uint32_t dst, const void* src) {
    asm volatile("cp.async.cg.shared.global [%0], [%1], 16;" :: "r"(dst), "l"(src));
}
__device__ __forceinline__ void cpasync_commit() {
    asm volatile("cp.async.commit_group;" ::: "memory");
}
__device__ __forceinline__ void cpasync_waitall() {
    asm volatile("cp.async.wait_all;" ::: "memory");
}

// ---------------- patchify (float4) ----------------
__global__ void patchify4_kernel(const float* __restrict__ x, float4* __restrict__ out)
{
    int idx4 = blockIdx.x * blockDim.x + threadIdx.x;
    const int total4 = ROWS_TOT * (D / 4);
    if (idx4 >= total4) return;
    int d4 = idx4 % (D / 4);
    int rem = idx4 / (D / 4);
    int n = rem % NPATCH;
    int b = rem / NPATCH;
    int d = d4 * 4;
    int c = d >> 8;
    int r2 = d & 255;
    int i = r2 >> 4;
    int j = r2 & 15;
    int hp = n / 14;
    int wp = n % 14;
    int src = ((b * 3 + c) * 224 + hp * 16 + i) * 224 + wp * 16 + j;
    out[idx4] = *reinterpret_cast<const float4*>(x + src);
}

// ---------------- Big GEMM: 128x128x16, 128 threads, f32x2 ----------------
#define GBM 128
#define GBN 128
#define GBK 16

__global__ __launch_bounds__(128, 2)
void big_gemm(const float* __restrict__ A, const float* __restrict__ B,
              const float* __restrict__ bias, float* __restrict__ C,
              int M, int K, int ldA, int ldB, int ldC,
              long long sA, long long sB, long long sBias, long long sC, int relu)
{
    long long bz = blockIdx.z;
    A += bz * sA;
    B += bz * sB;
    C += bz * sC;
    if (bias) bias += bz * sBias;

    __shared__ float As[2][GBK][GBM];
    __shared__ float Bs[2][GBK][GBN];

    int tid = threadIdx.x;
    int tx = tid & 15;
    int ty = tid >> 4;
    int rowBase = blockIdx.y * GBM;
    int colBase = blockIdx.x * GBN;

    unsigned long long acc[8][8];
#pragma unroll
    for (int i = 0; i < 8; i++)
#pragma unroll
        for (int j = 0; j < 8; j++) acc[i][j] = 0ull;

    const int nk = K / GBK;

    // ---- stage 0 ----
    {
#pragma unroll
        for (int u = 0; u < 4; u++) {
            int q = tid + 128 * u;
            int kb = q >> 5;
            int col4 = (q & 31) * 4;
            uint32_t dst = (uint32_t)__cvta_generic_to_shared(&Bs[0][kb][col4]);
            cpasync16(dst, B + (long long)kb * ldB + colBase + col4);
        }
        cpasync_commit();
#pragma unroll
        for (int u = 0; u < 4; u++) {
            int q = tid + 128 * u;
            int row = q >> 2;
            int kq = (q & 3) * 4;
            float4 av = make_float4(0.f, 0.f, 0.f, 0.f);
            if (rowBase + row < M)
                av = *reinterpret_cast<const float4*>(A + (long long)(rowBase + row) * ldA + kq);
            As[0][kq + 0][row] = av.x;
            As[0][kq + 1][row] = av.y;
            As[0][kq + 2][row] = av.z;
            As[0][kq + 3][row] = av.w;
        }
        cpasync_waitall();
        __syncthreads();
    }

    int buf = 0;
    for (int kt = 0; kt < nk; kt++) {
        float4 areg[4];
        bool has = (kt + 1) < nk;
        if (has) {
            int k0 = (kt + 1) * GBK;
#pragma unroll
            for (int u = 0; u < 4; u++) {
                int q = tid + 128 * u;
                int kb = q >> 5;
                int col4 = (q & 31) * 4;
                uint32_t dst = (uint32_t)__cvta_generic_to_shared(&Bs[buf ^ 1][kb][col4]);
                cpasync16(dst, B + (long long)(k0 + kb) * ldB + colBase + col4);
            }
            cpasync_commit();
#pragma unroll
            for (int u = 0; u < 4; u++) {
                int q = tid + 128 * u;
                int row = q >> 2;
                int kq = (q & 3) * 4;
                areg[u] = make_float4(0.f, 0.f, 0.f, 0.f);
                if (rowBase + row < M)
                    areg[u] = *reinterpret_cast<const float4*>(A + (long long)(rowBase + row) * ldA + k0 + kq);
            }
        }

#pragma unroll
        for (int kk = 0; kk < GBK; kk++) {
            const unsigned long long* ap =
                reinterpret_cast<const unsigned long long*>(&As[buf][kk][ty * 16]);
            unsigned long long a2[8];
#pragma unroll
            for (int i = 0; i < 8; i++) a2[i] = ap[i];
            float4 b0 = *reinterpret_cast<const float4*>(&Bs[buf][kk][tx * 4]);
            float4 b1 = *reinterpret_cast<const float4*>(&Bs[buf][kk][64 + tx * 4]);
            unsigned long long b2[8];
            b2[0] = pk2(b0.x); b2[1] = pk2(b0.y); b2[2] = pk2(b0.z); b2[3] = pk2(b0.w);
            b2[4] = pk2(b1.x); b2[5] = pk2(b1.y); b2[6] = pk2(b1.z); b2[7] = pk2(b1.w);
#pragma unroll
            for (int i = 0; i < 8; i++)
#pragma unroll
                for (int j = 0; j < 8; j++)
                    acc[i][j] = ffma2(a2[i], b2[j], acc[i][j]);
        }

        if (has) {
#pragma unroll
            for (int u = 0; u < 4; u++) {
                int q = tid + 128 * u;
                int row = q >> 2;
                int kq = (q & 3) * 4;
                As[buf ^ 1][kq + 0][row] = areg[u].x;
                As[buf ^ 1][kq + 1][row] = areg[u].y;
                As[buf ^ 1][kq + 2][row] = areg[u].z;
                As[buf ^ 1][kq + 3][row] = areg[u].w;
            }
            cpasync_waitall();
            __syncthreads();
            buf ^= 1;
        }
    }

    int colA = colBase + tx * 4;
    int colB = colA + 64;
    float4 ba = make_float4(0.f, 0.f, 0.f, 0.f), bb = ba;
    if (bias) {
        ba = *reinterpret_cast<const float4*>(bias + colA);
        bb = *reinterpret_cast<const float4*>(bias + colB);
    }
#pragma unroll
    for (int i = 0; i < 8; i++) {
        int r0 = rowBase + ty * 16 + 2 * i;
        float lo[8], hi[8];
#pragma unroll
        for (int j = 0; j < 8; j++) upk2(acc[i][j], lo[j], hi[j]);
        float4 vA0 = make_float4(lo[0] + ba.x, lo[1] + ba.y, lo[2] + ba.z, lo[3] + ba.w);
        float4 vB0 = make_float4(lo[4] + bb.x, lo[5] + bb.y, lo[6] + bb.z, lo[7] + bb.w);
        float4 vA1 = make_float4(hi[0] + ba.x, hi[1] + ba.y, hi[2] + ba.z, hi[3] + ba.w);
        float4 vB1 = make_float4(hi[4] + bb.x, hi[5] + bb.y, hi[6] + bb.z, hi[7] + bb.w);
        if (relu) {
            vA0.x = fmaxf(vA0.x, 0.f); vA0.y = fmaxf(vA0.y, 0.f); vA0.z = fmaxf(vA0.z, 0.f); vA0.w = fmaxf(vA0.w, 0.f);
            vB0.x = fmaxf(vB0.x, 0.f); vB0.y = fmaxf(vB0.y, 0.f); vB0.z = fmaxf(vB0.z, 0.f); vB0.w = fmaxf(vB0.w, 0.f);
            vA1.x = fmaxf(vA1.x, 0.f); vA1.y = fmaxf(vA1.y, 0.f); vA1.z = fmaxf(vA1.z, 0.f); vA1.w = fmaxf(vA1.w, 0.f);
            vB1.x = fmaxf(vB1.x, 0.f); vB1.y = fmaxf(vB1.y, 0.f); vB1.z = fmaxf(vB1.z, 0.f); vB1.w = fmaxf(vB1.w, 0.f);
        }
        if (r0 < M) {
            *reinterpret_cast<float4*>(C + (long long)r0 * ldC + colA) = vA0;
            *reinterpret_cast<float4*>(C + (long long)r0 * ldC + colB) = vB0;
        }
        if (r0 + 1 < M) {
            *reinterpret_cast<float4*>(C + (long long)(r0 + 1) * ldC + colA) = vA1;
            *reinterpret_cast<float4*>(C + (long long)(r0 + 1) * ldC + colB) = vB1;
        }
    }
}

// ---------------- Small GEMM (M=64) with split-K partials ----------------
#define SBK 32
__global__ __launch_bounds__(256)
void small_gemm(const float* __restrict__ A, const float* __restrict__ B0,
                const float* __restrict__ Bd, long long sB,
                float* __restrict__ part, int N, int Kc)
{
    int z = blockIdx.z;
    const float* B;
    if (B0) B = (z == 0) ? B0 : (Bd + (long long)(z - 1) * sB);
    else    B = Bd + (long long)z * sB;

    int S = gridDim.y;
    int sy = blockIdx.y;
    int colBase = blockIdx.x * 64;
    int k0 = sy * Kc;

    __shared__ float As[SBK][64];
    __shared__ float Bs[SBK][64];

    int tid = threadIdx.x;
    int tx = tid & 15;
    int ty = tid >> 4;

    float acc[4][4];
#pragma unroll
    for (int i = 0; i < 4; i++)
#pragma unroll
        for (int j = 0; j < 4; j++) acc[i][j] = 0.f;

    for (int kb = 0; kb < Kc; kb += SBK) {
#pragma unroll
        for (int u = 0; u < 2; u++) {
            int q = tid + 256 * u;
            int row = q >> 3;
            int kq = (q & 7) * 4;
            float4 av = *reinterpret_cast<const float4*>(A + (long long)row * 768 + k0 + kb + kq);
            As[kq + 0][row] = av.x;
            As[kq + 1][row] = av.y;
            As[kq + 2][row] = av.z;
            As[kq + 3][row] = av.w;
        }
#pragma unroll
        for (int u = 0; u < 2; u++) {
            int q = tid + 256 * u;
            int k = q >> 4;
            int col4 = (q & 15) * 4;
            *reinterpret_cast<float4*>(&Bs[k][col4]) =
                *reinterpret_cast<const float4*>(B + (long long)(k0 + kb + k) * N + colBase + col4);
        }
        __syncthreads();
#pragma unroll
        for (int k = 0; k < SBK; k++) {
            float4 a4 = *reinterpret_cast<const float4*>(&As[k][ty * 4]);
            float4 b4 = *reinterpret_cast<const float4*>(&Bs[k][tx * 4]);
            float ra[4] = {a4.x, a4.y, a4.z, a4.w};
            float rb[4] = {b4.x, b4.y, b4.z, b4.w};
#pragma unroll
            for (int i = 0; i < 4; i++)
#pragma unroll
                for (int j = 0; j < 4; j++)
                    acc[i][j] = fmaf(ra[i], rb[j], acc[i][j]);
        }
        __syncthreads();
    }

    float* dst = part + ((long long)(z * S + sy) * 64) * N;
#pragma unroll
    for (int i = 0; i < 4; i++) {
        int r = ty * 4 + i;
        *reinterpret_cast<float4*>(dst + (long long)r * N + colBase + tx * 4) =
            make_float4(acc[i][0], acc[i][1], acc[i][2], acc[i][3]);
    }
}

__global__ void reduce_kernel(const float* __restrict__ part, float* __restrict__ dst,
                              const float* __restrict__ bias, int N, int relu)
{
    int idx = blockIdx.x * blockDim.x + threadIdx.x;
    if (idx >= BATCH * N) return;
    float v = bias ? bias[idx % N] : 0.f;
#pragma unroll
    for (int s = 0; s < SPLITS; s++) v += part[(long long)s * BATCH * N + idx];
    if (relu) v = fmaxf(v, 0.f);
    dst[idx] = v;
}

__global__ void coefs_kernel(const float* __restrict__ mw2, const float* __restrict__ mb2)
{
    int t = threadIdx.x;
    int b = t >> 3;
    int j = t & 7;
    float s = mb2[j];
    for (int k = 0; k < HMETA; k++)
        s = fmaf(g_hid[b * HMETA + k], mw2[k * T + j], s);
    g_coefs[b * T + j] = s;
}

__global__ void pool4_kernel(const float4* __restrict__ h, float4* __restrict__ pooled)
{
    int idx = blockIdx.x * blockDim.x + threadIdx.x;
    const int D4 = D / 4;
    if (idx >= BATCH * D4) return;
    int d4 = idx % D4;
    int b = idx / D4;
    const float4* p = h + (long long)b * NPATCH * D4 + d4;
    float4 s = make_float4(0.f, 0.f, 0.f, 0.f);
    for (int n = 0; n < NPATCH; n++) {
        float4 v = p[(long long)n * D4];
        s.x += v.x; s.y += v.y; s.z += v.z; s.w += v.w;
    }
    const float inv = 1.0f / NPATCH;
    pooled[idx] = make_float4(s.x * inv, s.y * inv, s.z * inv, s.w * inv);
}

__global__ void mixbias_kernel(const float* __restrict__ b1, const float* __restrict__ db1,
                               const float* __restrict__ b2, const float* __restrict__ db2)
{
    int idx = blockIdx.x * blockDim.x + threadIdx.x;
    if (idx >= BATCH * D) return;
    int j = idx % D;
    int b = idx / D;
    float c[T];
#pragma unroll
    for (int t = 0; t < T; t++) c[t] = g_coefs[b * T + t];
    float v1 = b1[j], v2 = b2[j];
#pragma unroll
    for (int t = 0; t < T; t++) {
        v1 = fmaf(c[t], db1[t * D + j], v1);
        v2 = fmaf(c[t], db2[t * D + j], v2);
    }
    g_nb1[idx] = v1;
    g_nb2[idx] = v2;
}

__global__ void mixw1_kernel(const float* __restrict__ W1, const float* __restrict__ dW1)
{
    long long idx4 = (long long)blockIdx.x * blockDim.x + threadIdx.x;
    const long long per_b4 = DD / 4;
    const long long total4 = (long long)BATCH * per_b4;
    if (idx4 >= total4) return;
    long long b = idx4 / per_b4;
    long long r = idx4 - b * per_b4;

    float c[T];
#pragma unroll
    for (int t = 0; t < T; t++) c[t] = g_coefs[b * T + t];

    float4 v = reinterpret_cast<const float4*>(W1)[r];
#pragma unroll
    for (int t = 0; t < T; t++) {
        float4 dv = reinterpret_cast<const float4*>(dW1)[(long long)t * per_b4 + r];
        v.x = fmaf(c[t], dv.x, v.x);
        v.y = fmaf(c[t], dv.y, v.y);
        v.z = fmaf(c[t], dv.z, v.z);
        v.w = fmaf(c[t], dv.w, v.w);
    }
    reinterpret_cast<float4*>(g_mixW1)[b * per_b4 + r] = v;
}

__global__ void final_out_kernel(const float* __restrict__ part, float* __restrict__ out)
{
    int idx = blockIdx.x * blockDim.x + threadIdx.x;
    if (idx >= BATCH * D) return;
    int b = idx / D;
    const int SLAB = BATCH * D;
    float v = g_nb2[idx];
#pragma unroll
    for (int s = 0; s < SPLITS; s++) v += part[(long long)s * SLAB + idx];
#pragma unroll
    for (int t = 0; t < T; t++) {
        float qv = 0.f;
#pragma unroll
        for (int s = 0; s < SPLITS; s++)
            qv += part[(long long)((t + 1) * SPLITS + s) * SLAB + idx];
        v = fmaf(g_coefs[b * T + t], qv, v);
    }
    out[idx] = v;
}

extern "C" void kernel_launch(void* const* d_in, const int* in_sizes, int n_in,
                              void* d_out, int out_size)
{
    const float* x   = (const float*)d_in[0];
    const float* W1  = (const float*)d_in[1];
    const float* b1  = (const float*)d_in[2];
    const float* W2  = (const float*)d_in[3];
    const float* b2  = (const float*)d_in[4];
    const float* dW1 = (const float*)d_in[5];
    const float* db1 = (const float*)d_in[6];
    const float* dW2 = (const float*)d_in[7];
    const float* db2 = (const float*)d_in[8];
    const float* mw1 = (const float*)d_in[9];
    const float* mb1 = (const float*)d_in[10];
    const float* mw2 = (const float*)d_in[11];
    const float* mb2 = (const float*)d_in[12];
    float* out = (float*)d_out;

    float *patches, *h, *pooled, *pooled2, *base, *hid, *mixW1, *part, *nb1;
    cudaGetSymbolAddress((void**)&patches, g_patches);
    cudaGetSymbolAddress((void**)&h,       g_h);
    cudaGetSymbolAddress((void**)&pooled,  g_pooled);
    cudaGetSymbolAddress((void**)&pooled2, g_pooled2);
    cudaGetSymbolAddress((void**)&base,    g_base);
    cudaGetSymbolAddress((void**)&hid,     g_hid);
    cudaGetSymbolAddress((void**)&mixW1,   g_mixW1);
    cudaGetSymbolAddress((void**)&part,    g_part);
    cudaGetSymbolAddress((void**)&nb1,     g_nb1);

    const int TPB = 256;

    // 1) patchify
    {
        int total4 = ROWS_TOT * (D / 4);
        patchify4_kernel<<<(total4 + TPB - 1) / TPB, TPB>>>(x, (float4*)patches);
    }

    // 2) h = relu(patches @ W1 + b1)
    big_gemm<<<dim3(D / GBN, (ROWS_TOT + GBM - 1) / GBM, 1), 128>>>(
        patches, W1, b1, h, ROWS_TOT, D, D, D, D, 0, 0, 0, 0, 1);

    // 3) pooled = mean_n h
    pool4_kernel<<<(BATCH * D / 4 + TPB - 1) / TPB, TPB>>>((const float4*)h, (float4*)pooled);

    // 4) base = pooled @ W2 + b2
    small_gemm<<<dim3(D / 64, SPLITS, 1), 256>>>(pooled, W2, nullptr, 0, part, D, D / SPLITS);
    reduce_kernel<<<(BATCH * D + TPB - 1) / TPB, TPB>>>(part, base, b2, D, 0);

    // 5) hid = relu(base @ mw1 + mb1)
    small_gemm<<<dim3(HMETA / 64, SPLITS, 1), 256>>>(base, mw1, nullptr, 0, part, HMETA, D / SPLITS);
    reduce_kernel<<<(BATCH * HMETA + TPB - 1) / TPB, TPB>>>(part, hid, mb1, HMETA, 1);

    // 6) coefs
    coefs_kernel<<<1, 512>>>(mw2, mb2);

    // 7) mixed biases
    mixbias_kernel<<<(BATCH * D + TPB - 1) / TPB, TPB>>>(b1, db1, b2, db2);

    // 8) mixW1
    {
        long long total4 = (long long)BATCH * (DD / 4);
        mixw1_kernel<<<(unsigned)((total4 + TPB - 1) / TPB), TPB>>>(W1, dW1);
    }

    // 9) h = relu(patches @ mixW1[b] + nb1[b])
    big_gemm<<<dim3(D / GBN, (NPATCH + GBM - 1) / GBM, BATCH), 128>>>(
        patches, mixW1, nb1, h, NPATCH, D, D, D, D,
        (long long)NPATCH * D, (long long)DD, (long long)D, (long long)NPATCH * D, 1);

    // 10) pooled2
    pool4_kernel<<<(BATCH * D / 4 + TPB - 1) / TPB, TPB>>>((const float4*)h, (float4*)pooled2);

    // 11+12) q (dW2 tasks) + W2 head via z=0
    small_gemm<<<dim3(D / 64, SPLITS, T + 1), 256>>>(pooled2, W2, dW2, (long long)DD, part, D, D / SPLITS);

    // 13) final output
    final_out_kernel<<<(BATCH * D + TPB - 1) / TPB, TPB>>>(part, out);
}

// round 5
// speedup vs baseline: 3.8070x; 1.8437x over previous
#include <cuda_runtime.h>
#include <cstdint>

// ---------------- Problem constants ----------------
#define BATCH 64
#define NPATCH 196
#define D 768
#define T 8
#define HMETA 192
#define ROWS_TOT (BATCH * NPATCH)   // 12544
#define DD (D * D)
#define SPLITS 6
#define NKT 24                      // 768 / 32 K-chunks
#define ROWTILES1 98                // 12544 / 128

// ---------------- Device scratch ----------------
__device__ float g_patches[(size_t)(ROWS_TOT + 64) * D];  // padded rows stay zero
__device__ float g_W1T[DD];
__device__ float g_dW1T[(size_t)T * DD];
__device__ float g_mixW1T[(size_t)BATCH * DD];            // 151 MB
__device__ float g_pooled[BATCH * D];
__device__ float g_pooled2[BATCH * D];
__device__ float g_base[BATCH * D];
__device__ float g_hid[BATCH * HMETA];
__device__ float g_coefs[BATCH * T];
__device__ float g_nb1[BATCH * D];
__device__ float g_nb2[BATCH * D];
__device__ float g_part[(size_t)(T + 1) * SPLITS * BATCH * D];
__device__ float g_p1part[(size_t)ROWTILES1 * 2 * D];
__device__ float g_p2part[(size_t)BATCH * 2 * D];

// ---------------- PTX helpers (all sm_80+ baseline) ----------------
__device__ __forceinline__ float rna_tf32(float x) {
    float y;
    asm("cvt.rna.tf32.f32 %0, %1;" : "=f"(y) : "f"(x));
    return y;
}
__device__ __forceinline__ void cpasync16(uint32_t dst, const void* src) {
    asm volatile("cp.async.cg.shared.global [%0], [%1], 16;" :: "r"(dst), "l"(src));
}
__device__ __forceinline__ void cpasync_commit() {
    asm volatile("cp.async.commit_group;" ::: "memory");
}
__device__ __forceinline__ void mma16n8k8(float* c, const float* a, const float* b) {
    asm volatile("mma.sync.aligned.m16n8k8.row.col.f32.tf32.tf32.f32 "
        "{%0,%1,%2,%3}, {%4,%5,%6,%7}, {%8,%9}, {%0,%1,%2,%3};"
        : "+f"(c[0]), "+f"(c[1]), "+f"(c[2]), "+f"(c[3])
        : "r"(__float_as_uint(a[0])), "r"(__float_as_uint(a[1])),
          "r"(__float_as_uint(a[2])), "r"(__float_as_uint(a[3])),
          "r"(__float_as_uint(b[0])), "r"(__float_as_uint(b[1])));
}

// ---------------- SMEM layout for mma_gemm_pool ----------------
// 4 buffers of 128x36 floats (A0,B0,A1,B1). Epilogue reuses region as
// sD[128][132] + sRed[2][2][128].
#define SSTRIDE 36
#define STAGEF (128 * SSTRIDE)            // 4608 floats = 18432 bytes
#define SM_BYTES (4 * STAGEF * 4)         // 73728 bytes
#define SRED_OFF (128 * 132)              // float offset 16896

// load one 128x32 tile (row-major, ld = D) into smem [128][36]
__device__ __forceinline__ void load_tile32(float* dstBase, const float* src,
                                            int tid, int k0)
{
#pragma unroll
    for (int u = 0; u < 4; u++) {
        int q = tid + 256 * u;
        int row = q >> 3;
        int c4 = q & 7;
        uint32_t dst = (uint32_t)__cvta_generic_to_shared(dstBase + row * SSTRIDE + c4 * 4);
        cpasync16(dst, src + (size_t)row * D + k0 + c4 * 4);
    }
}

// ---------------- tf32 mma GEMM + fused relu + mean-pool partials ----------------
// D_tile = A[128xK] @ B_tile^T (B stored [N,K] K-major).
// Epilogue: relu(D + bias) / 196, column-summed into per-tile partials.
__global__ __launch_bounds__(256, 2)
void mma_gemm_pool(const float* __restrict__ A, const float* __restrict__ B,
                   const float* __restrict__ bias, float* __restrict__ part,
                   long long sA, long long sB, int biasPerZ,
                   int Mvalid, int rowIsGlobal)
{
    extern __shared__ float sm[];
    float* bufA[2] = { sm,              sm + 2 * STAGEF };
    float* bufB[2] = { sm + STAGEF,     sm + 3 * STAGEF };

    int tid = threadIdx.x;
    int wid = tid >> 5;
    int lane = tid & 31;
    int q = lane >> 2;      // 0..7
    int t = lane & 3;       // 0..3
    int warpRow = (wid & 3) * 32;
    int warpCol = (wid >> 2) * 64;

    int rowBase = blockIdx.y * 128;
    int colBase = blockIdx.x * 128;
    long long z = blockIdx.z;
    const float* Arow = A + z * sA + (size_t)rowBase * D;
    const float* Brow = B + z * sB + (size_t)colBase * D;
    const float* biasp = bias + (biasPerZ ? z * (long long)D : 0) + colBase;

    float acc[2][8][4];
#pragma unroll
    for (int mt = 0; mt < 2; mt++)
#pragma unroll
        for (int nt = 0; nt < 8; nt++)
#pragma unroll
            for (int e = 0; e < 4; e++) acc[mt][nt][e] = 0.f;

    // preload chunks 0, 1
    load_tile32(bufA[0], Arow, tid, 0);
    load_tile32(bufB[0], Brow, tid, 0);
    cpasync_commit();
    load_tile32(bufA[1], Arow, tid, 32);
    load_tile32(bufB[1], Brow, tid, 32);
    cpasync_commit();

    for (int kt = 0; kt < NKT; kt++) {
        int buf = kt & 1;
        if (kt < NKT - 2) asm volatile("cp.async.wait_group 1;" ::: "memory");
        else              asm volatile("cp.async.wait_group 0;" ::: "memory");
        __syncthreads();

        const float* As = bufA[buf];
        const float* Bs = bufB[buf];
#pragma unroll
        for (int ks = 0; ks < 4; ks++) {
            int k0 = ks * 8;
            float a[2][4];
#pragma unroll
            for (int mt = 0; mt < 2; mt++) {
                int r = warpRow + mt * 16 + q;
                a[mt][0] = As[(size_t)r * SSTRIDE + k0 + t];
                a[mt][1] = As[(size_t)(r + 8) * SSTRIDE + k0 + t];
                a[mt][2] = As[(size_t)r * SSTRIDE + k0 + t + 4];
                a[mt][3] = As[(size_t)(r + 8) * SSTRIDE + k0 + t + 4];
            }
            float b[8][2];
#pragma unroll
            for (int nt = 0; nt < 8; nt++) {
                int n = warpCol + nt * 8 + q;
                b[nt][0] = Bs[(size_t)n * SSTRIDE + k0 + t];
                b[nt][1] = Bs[(size_t)n * SSTRIDE + k0 + t + 4];
            }
#pragma unroll
            for (int mt = 0; mt < 2; mt++)
#pragma unroll
                for (int nt = 0; nt < 8; nt++)
                    mma16n8k8(acc[mt][nt], a[mt], b[nt]);
        }
        __syncthreads();   // all warps done reading buf before overwrite

        if (kt + 2 < NKT) {
            int k0 = (kt + 2) * 32;
            load_tile32(bufA[buf], Arow, tid, k0);
            load_tile32(bufB[buf], Brow, tid, k0);
            cpasync_commit();
        }
    }

    // ---- epilogue: stage relu(D+bias)/196 into smem (masked rows) ----
    float* sD = sm;   // 128 x 132
    const float invR = 1.0f / (float)NPATCH;
#pragma unroll
    for (int mt = 0; mt < 2; mt++) {
        int r0 = warpRow + mt * 16 + q;
        int r1 = r0 + 8;
        bool v0 = (rowBase + r0) < Mvalid;
        bool v1 = (rowBase + r1) < Mvalid;
#pragma unroll
        for (int nt = 0; nt < 8; nt++) {
            int c = warpCol + nt * 8 + t * 2;
            float bv0 = biasp[c], bv1 = biasp[c + 1];
            float x0 = fmaxf(acc[mt][nt][0] + bv0, 0.f) * invR;
            float x1 = fmaxf(acc[mt][nt][1] + bv1, 0.f) * invR;
            float x2 = fmaxf(acc[mt][nt][2] + bv0, 0.f) * invR;
            float x3 = fmaxf(acc[mt][nt][3] + bv1, 0.f) * invR;
            sD[(size_t)r0 * 132 + c]     = v0 ? x0 : 0.f;
            sD[(size_t)r0 * 132 + c + 1] = v0 ? x1 : 0.f;
            sD[(size_t)r1 * 132 + c]     = v1 ? x2 : 0.f;
            sD[(size_t)r1 * 132 + c + 1] = v1 ? x3 : 0.f;
        }
    }
    __syncthreads();

    // ---- two-phase column reduction ----
    float* sRed = sm + SRED_OFF;   // [half][slot][128]
    {
        int col = tid & 127;
        int half = tid >> 7;
        int rbound = 128;   // rows < rbound -> slot 0
        if (rowIsGlobal) {
            int b0 = rowBase / NPATCH;
            rbound = (b0 + 1) * NPATCH - rowBase;
            if (rbound > 128) rbound = 128;
        }
        float a0 = 0.f, a1 = 0.f;
        int rs = half * 64;
        for (int r = rs; r < rs + 64; r++) {
            float v = sD[(size_t)r * 132 + col];
            if (r < rbound) a0 += v; else a1 += v;
        }
        sRed[(half * 2 + 0) * 128 + col] = a0;
        sRed[(half * 2 + 1) * 128 + col] = a1;
    }
    __syncthreads();
    if (tid < 128) {
        float s0 = sRed[0 * 128 + tid] + sRed[2 * 128 + tid];
        float s1 = sRed[1 * 128 + tid] + sRed[3 * 128 + tid];
        int col = colBase + tid;
        if (rowIsGlobal) {
            part[((size_t)blockIdx.y * 2 + 0) * D + col] = s0;
            part[((size_t)blockIdx.y * 2 + 1) * D + col] = s1;
        } else {
            part[((size_t)z * gridDim.y + blockIdx.y) * D + col] = s0;
        }
    }
}

// ---------------- combine pool partials ----------------
__global__ void combine1_kernel(const float* __restrict__ part, float* __restrict__ pooled)
{
    int idx = blockIdx.x * blockDim.x + threadIdx.x;
    if (idx >= BATCH * D) return;
    int j = idx % D;
    int b = idx / D;
    int r0 = (b * NPATCH) / 128;
    int r1 = (b * NPATCH + NPATCH - 1) / 128;
    float s = 0.f;
    for (int ry = r0; ry <= r1; ry++) {
        int tb = (ry * 128) / NPATCH;
        int slot = (b == tb) ? 0 : 1;
        s += part[((size_t)ry * 2 + slot) * D + j];
    }
    pooled[idx] = s;
}

__global__ void combine2_kernel(const float* __restrict__ part, float* __restrict__ pooled)
{
    int idx = blockIdx.x * blockDim.x + threadIdx.x;
    if (idx >= BATCH * D) return;
    int j = idx % D;
    int b = idx / D;
    pooled[idx] = part[((size_t)b * 2 + 0) * D + j] + part[((size_t)b * 2 + 1) * D + j];
}

// ---------------- patchify (float4, tf32-rounded) ----------------
__global__ void patchify4_kernel(const float* __restrict__ x, float4* __restrict__ out)
{
    int idx4 = blockIdx.x * blockDim.x + threadIdx.x;
    const int total4 = ROWS_TOT * (D / 4);
    if (idx4 >= total4) return;
    int d4 = idx4 % (D / 4);
    int rem = idx4 / (D / 4);
    int n = rem % NPATCH;
    int b = rem / NPATCH;
    int d = d4 * 4;
    int c = d >> 8;
    int r2 = d & 255;
    int i = r2 >> 4;
    int j = r2 & 15;
    int hp = n / 14;
    int wp = n % 14;
    int src = ((b * 3 + c) * 224 + hp * 16 + i) * 224 + wp * 16 + j;
    float4 v = *reinterpret_cast<const float4*>(x + src);
    v.x = rna_tf32(v.x); v.y = rna_tf32(v.y); v.z = rna_tf32(v.z); v.w = rna_tf32(v.w);
    out[idx4] = v;
}

// ---------------- transpose W1 / dW1 -> [N,K], tf32-rounded ----------------
__global__ void transpose_kernel(const float* __restrict__ W1, const float* __restrict__ dW1,
                                 float* __restrict__ W1T, float* __restrict__ dW1T)
{
    __shared__ float tile[32][33];
    int z = blockIdx.z;
    const float* src = (z == 0) ? W1 : dW1 + (size_t)(z - 1) * DD;
    float* dst = (z == 0) ? W1T : dW1T + (size_t)(z - 1) * DD;
    int xx = blockIdx.x * 32 + threadIdx.x;
    int y0 = blockIdx.y * 32;
    for (int i = threadIdx.y; i < 32; i += 8)
        tile[i][threadIdx.x] = src[(size_t)(y0 + i) * D + xx];
    __syncthreads();
    int ox = blockIdx.y * 32 + threadIdx.x;
    int oy0 = blockIdx.x * 32;
    for (int i = threadIdx.y; i < 32; i += 8)
        dst[(size_t)(oy0 + i) * D + ox] = rna_tf32(tile[threadIdx.x][i]);
}

// ---------------- Small GEMM (M=64) with split-K partials ----------------
#define SBK 32
__global__ __launch_bounds__(256)
void small_gemm(const float* __restrict__ A, const float* __restrict__ B0,
                const float* __restrict__ Bd, long long sB,
                float* __restrict__ part, int N, int Kc)
{
    int z = blockIdx.z;
    const float* B;
    if (B0) B = (z == 0) ? B0 : (Bd + (long long)(z - 1) * sB);
    else    B = Bd + (long long)z * sB;

    int S = gridDim.y;
    int sy = blockIdx.y;
    int colBase = blockIdx.x * 64;
    int k0 = sy * Kc;

    __shared__ float As[SBK][64];
    __shared__ float Bs[SBK][64];

    int tid = threadIdx.x;
    int tx = tid & 15;
    int ty = tid >> 4;

    float acc[4][4];
#pragma unroll
    for (int i = 0; i < 4; i++)
#pragma unroll
        for (int j = 0; j < 4; j++) acc[i][j] = 0.f;

    for (int kb = 0; kb < Kc; kb += SBK) {
#pragma unroll
        for (int u = 0; u < 2; u++) {
            int qq = tid + 256 * u;
            int row = qq >> 3;
            int kq = (qq & 7) * 4;
            float4 av = *reinterpret_cast<const float4*>(A + (long long)row * D + k0 + kb + kq);
            As[kq + 0][row] = av.x;
            As[kq + 1][row] = av.y;
            As[kq + 2][row] = av.z;
            As[kq + 3][row] = av.w;
        }
#pragma unroll
        for (int u = 0; u < 2; u++) {
            int qq = tid + 256 * u;
            int k = qq >> 4;
            int col4 = (qq & 15) * 4;
            *reinterpret_cast<float4*>(&Bs[k][col4]) =
                *reinterpret_cast<const float4*>(B + (long long)(k0 + kb + k) * N + colBase + col4);
        }
        __syncthreads();
#pragma unroll
        for (int k = 0; k < SBK; k++) {
            float4 a4 = *reinterpret_cast<const float4*>(&As[k][ty * 4]);
            float4 b4 = *reinterpret_cast<const float4*>(&Bs[k][tx * 4]);
            float ra[4] = {a4.x, a4.y, a4.z, a4.w};
            float rb[4] = {b4.x, b4.y, b4.z, b4.w};
#pragma unroll
            for (int i = 0; i < 4; i++)
#pragma unroll
                for (int j = 0; j < 4; j++)
                    acc[i][j] = fmaf(ra[i], rb[j], acc[i][j]);
        }
        __syncthreads();
    }

    float* dst = part + ((long long)(z * S + sy) * 64) * N;
#pragma unroll
    for (int i = 0; i < 4; i++) {
        int r = ty * 4 + i;
        *reinterpret_cast<float4*>(dst + (long long)r * N + colBase + tx * 4) =
            make_float4(acc[i][0], acc[i][1], acc[i][2], acc[i][3]);
    }
}

__global__ void reduce_kernel(const float* __restrict__ part, float* __restrict__ dst,
                              const float* __restrict__ bias, int N, int relu)
{
    int idx = blockIdx.x * blockDim.x + threadIdx.x;
    if (idx >= BATCH * N) return;
    float v = bias ? bias[idx % N] : 0.f;
#pragma unroll
    for (int s = 0; s < SPLITS; s++) v += part[(long long)s * BATCH * N + idx];
    if (relu) v = fmaxf(v, 0.f);
    dst[idx] = v;
}

__global__ void coefs_kernel(const float* __restrict__ mw2, const float* __restrict__ mb2)
{
    int t = threadIdx.x;
    int b = t >> 3;
    int j = t & 7;
    float s = mb2[j];
    for (int k = 0; k < HMETA; k++)
        s = fmaf(g_hid[b * HMETA + k], mw2[k * T + j], s);
    g_coefs[b * T + j] = s;
}

__global__ void mixbias_kernel(const float* __restrict__ b1, const float* __restrict__ db1,
                               const float* __restrict__ b2, const float* __restrict__ db2)
{
    int idx = blockIdx.x * blockDim.x + threadIdx.x;
    if (idx >= BATCH * D) return;
    int j = idx % D;
    int b = idx / D;
    float c[T];
#pragma unroll
    for (int t = 0; t < T; t++) c[t] = g_coefs[b * T + t];
    float v1 = b1[j], v2 = b2[j];
#pragma unroll
    for (int t = 0; t < T; t++) {
        v1 = fmaf(c[t], db1[t * D + j], v1);
        v2 = fmaf(c[t], db2[t * D + j], v2);
    }
    g_nb1[idx] = v1;
    g_nb2[idx] = v2;
}

// mixW1T[b] = W1T + sum_t c[b,t] dW1T[t], tf32-rounded output
__global__ void mixw1t_kernel(void)
{
    long long idx4 = (long long)blockIdx.x * blockDim.x + threadIdx.x;
    const long long per_b4 = DD / 4;
    const long long total4 = (long long)BATCH * per_b4;
    if (idx4 >= total4) return;
    long long b = idx4 / per_b4;
    long long r = idx4 - b * per_b4;

    float c[T];
#pragma unroll
    for (int t = 0; t < T; t++) c[t] = g_coefs[b * T + t];

    float4 v = reinterpret_cast<const float4*>(g_W1T)[r];
#pragma unroll
    for (int t = 0; t < T; t++) {
        float4 dv = reinterpret_cast<const float4*>(g_dW1T)[(long long)t * per_b4 + r];
        v.x = fmaf(c[t], dv.x, v.x);
        v.y = fmaf(c[t], dv.y, v.y);
        v.z = fmaf(c[t], dv.z, v.z);
        v.w = fmaf(c[t], dv.w, v.w);
    }
    v.x = rna_tf32(v.x); v.y = rna_tf32(v.y); v.z = rna_tf32(v.z); v.w = rna_tf32(v.w);
    reinterpret_cast<float4*>(g_mixW1T)[b * per_b4 + r] = v;
}

__global__ void final_out_kernel(const float* __restrict__ part, float* __restrict__ out)
{
    int idx = blockIdx.x * blockDim.x + threadIdx.x;
    if (idx >= BATCH * D) return;
    int b = idx / D;
    const int SLAB = BATCH * D;
    float v = g_nb2[idx];
#pragma unroll
    for (int s = 0; s < SPLITS; s++) v += part[(long long)s * SLAB + idx];
#pragma unroll
    for (int t = 0; t < T; t++) {
        float qv = 0.f;
#pragma unroll
        for (int s = 0; s < SPLITS; s++)
            qv += part[(long long)((t + 1) * SPLITS + s) * SLAB + idx];
        v = fmaf(g_coefs[b * T + t], qv, v);
    }
    out[idx] = v;
}

// ---------------- launch ----------------
extern "C" void kernel_launch(void* const* d_in, const int* in_sizes, int n_in,
                              void* d_out, int out_size)
{
    const float* x   = (const float*)d_in[0];
    const float* W1  = (const float*)d_in[1];
    const float* b1  = (const float*)d_in[2];
    const float* W2  = (const float*)d_in[3];
    const float* b2  = (const float*)d_in[4];
    const float* dW1 = (const float*)d_in[5];
    const float* db1 = (const float*)d_in[6];
    const float* dW2 = (const float*)d_in[7];
    const float* db2 = (const float*)d_in[8];
    const float* mw1 = (const float*)d_in[9];
    const float* mb1 = (const float*)d_in[10];
    const float* mw2 = (const float*)d_in[11];
    const float* mb2 = (const float*)d_in[12];
    float* out = (float*)d_out;

    float *patches, *W1T, *dW1T, *mixW1T, *pooled, *pooled2, *base, *hid;
    float *part, *p1part, *p2part, *nb1;
    cudaGetSymbolAddress((void**)&patches, g_patches);
    cudaGetSymbolAddress((void**)&W1T,     g_W1T);
    cudaGetSymbolAddress((void**)&dW1T,    g_dW1T);
    cudaGetSymbolAddress((void**)&mixW1T,  g_mixW1T);
    cudaGetSymbolAddress((void**)&pooled,  g_pooled);
    cudaGetSymbolAddress((void**)&pooled2, g_pooled2);
    cudaGetSymbolAddress((void**)&base,    g_base);
    cudaGetSymbolAddress((void**)&hid,     g_hid);
    cudaGetSymbolAddress((void**)&part,    g_part);
    cudaGetSymbolAddress((void**)&p1part,  g_p1part);
    cudaGetSymbolAddress((void**)&p2part,  g_p2part);
    cudaGetSymbolAddress((void**)&nb1,     g_nb1);

    cudaFuncSetAttribute(mma_gemm_pool, cudaFuncAttributeMaxDynamicSharedMemorySize, SM_BYTES);

    const int TPB = 256;

    // 1) patchify (tf32-rounded)
    {
        int total4 = ROWS_TOT * (D / 4);
        patchify4_kernel<<<(total4 + TPB - 1) / TPB, TPB>>>(x, (float4*)patches);
    }

    // 2) transpose W1 -> W1T, dW1 -> dW1T (tf32-rounded)
    transpose_kernel<<<dim3(D / 32, D / 32, T + 1), dim3(32, 8)>>>(W1, dW1, W1T, dW1T);

    // 3) GEMM1 (mma.sync tf32) fused relu+pool partials
    mma_gemm_pool<<<dim3(D / 128, ROWTILES1, 1), 256, SM_BYTES>>>(
        patches, W1T, b1, p1part, 0, 0, 0, ROWS_TOT, 1);
    combine1_kernel<<<(BATCH * D + TPB - 1) / TPB, TPB>>>(p1part, pooled);

    // 4) base = pooled @ W2 + b2
    small_gemm<<<dim3(D / 64, SPLITS, 1), 256>>>(pooled, W2, nullptr, 0, part, D, D / SPLITS);
    reduce_kernel<<<(BATCH * D + TPB - 1) / TPB, TPB>>>(part, base, b2, D, 0);

    // 5) hid = relu(base @ mw1 + mb1)
    small_gemm<<<dim3(HMETA / 64, SPLITS, 1), 256>>>(base, mw1, nullptr, 0, part, HMETA, D / SPLITS);
    reduce_kernel<<<(BATCH * HMETA + TPB - 1) / TPB, TPB>>>(part, hid, mb1, HMETA, 1);

    // 6) coefs
    coefs_kernel<<<1, 512>>>(mw2, mb2);

    // 7) mixed biases
    mixbias_kernel<<<(BATCH * D + TPB - 1) / TPB, TPB>>>(b1, db1, b2, db2);

    // 8) mixW1T (tf32-rounded)
    {
        long long total4 = (long long)BATCH * (DD / 4);
        mixw1t_kernel<<<(unsigned)((total4 + TPB - 1) / TPB), TPB>>>();
    }

    // 9) GEMM2 (mma.sync tf32, batched) fused relu+pool partials
    mma_gemm_pool<<<dim3(D / 128, 2, BATCH), 256, SM_BYTES>>>(
        patches, mixW1T, nb1, p2part,
        (long long)NPATCH * D, (long long)DD, 1, NPATCH, 0);
    combine2_kernel<<<(BATCH * D + TPB - 1) / TPB, TPB>>>(p2part, pooled2);

    // 10+11) q (dW2 tasks) + W2 head via z=0 (split-K partials)
    small_gemm<<<dim3(D / 64, SPLITS, T + 1), 256>>>(pooled2, W2, dW2, (long long)DD, part, D, D / SPLITS);

    // 12) final output
    final_out_kernel<<<(BATCH * D + TPB - 1) / TPB, TPB>>>(part, out);
}

// round 6
// speedup vs baseline: 4.2204x; 1.1086x over previous
#include <cuda_runtime.h>
#include <cstdint>

// ---------------- Problem constants ----------------
#define BATCH 64
#define NPATCH 196
#define D 768
#define T 8
#define HMETA 192
#define ROWS_TOT (BATCH * NPATCH)   // 12544
#define DD (D * D)
#define SPLITS 6
#define NKT 24                      // 768 / 32 K-chunks
#define ROWTILES1 98                // 12544 / 128

// ---------------- Device scratch ----------------
__device__ float g_patches[(size_t)(ROWS_TOT + 64) * D];  // padded rows stay zero
__device__ float g_W1T[DD];
__device__ float g_dW1T[(size_t)T * DD];
__device__ float g_mixW1T[(size_t)BATCH * DD];            // 151 MB
__device__ float g_pooled[BATCH * D];
__device__ float g_pooled2[BATCH * D];
__device__ float g_base[BATCH * D];
__device__ float g_hid[BATCH * HMETA];
__device__ float g_coefs[BATCH * T];
__device__ float g_nb1[BATCH * D];
__device__ float g_nb2[BATCH * D];
__device__ float g_part[(size_t)(T + 1) * SPLITS * BATCH * D];
__device__ float g_p1part[(size_t)ROWTILES1 * 2 * D];
__device__ float g_p2part[(size_t)BATCH * 2 * D];

// ---------------- PTX helpers (all sm_80+ baseline) ----------------
__device__ __forceinline__ float rna_tf32(float x) {
    float y;
    asm("cvt.rna.tf32.f32 %0, %1;" : "=f"(y) : "f"(x));
    return y;
}
__device__ __forceinline__ void cpasync16(uint32_t dst, const void* src) {
    asm volatile("cp.async.cg.shared.global [%0], [%1], 16;" :: "r"(dst), "l"(src));
}
__device__ __forceinline__ void cpasync_commit() {
    asm volatile("cp.async.commit_group;" ::: "memory");
}
__device__ __forceinline__ void mma16n8k8(float* c, const float* a, const float* b) {
    asm volatile("mma.sync.aligned.m16n8k8.row.col.f32.tf32.tf32.f32 "
        "{%0,%1,%2,%3}, {%4,%5,%6,%7}, {%8,%9}, {%0,%1,%2,%3};"
        : "+f"(c[0]), "+f"(c[1]), "+f"(c[2]), "+f"(c[3])
        : "r"(__float_as_uint(a[0])), "r"(__float_as_uint(a[1])),
          "r"(__float_as_uint(a[2])), "r"(__float_as_uint(a[3])),
          "r"(__float_as_uint(b[0])), "r"(__float_as_uint(b[1])));
}

// ---------------- SMEM layout for mma_gemm_pool ----------------
#define SSTRIDE 36
#define STAGEF (128 * SSTRIDE)            // 4608 floats = 18432 bytes
#define SM_BYTES (4 * STAGEF * 4)         // 73728 bytes
#define SRED_OFF (128 * 132)              // float offset 16896

// load one 128x32 tile (row-major, ld = D) into smem [128][36]
__device__ __forceinline__ void load_tile32(float* dstBase, const float* src,
                                            int tid, int k0)
{
#pragma unroll
    for (int u = 0; u < 4; u++) {
        int q = tid + 256 * u;
        int row = q >> 3;
        int c4 = q & 7;
        uint32_t dst = (uint32_t)__cvta_generic_to_shared(dstBase + row * SSTRIDE + c4 * 4);
        cpasync16(dst, src + (size_t)row * D + k0 + c4 * 4);
    }
}

// ---------------- tf32 mma GEMM + fused relu + mean-pool partials ----------------
__global__ __launch_bounds__(256, 2)
void mma_gemm_pool(const float* __restrict__ A, const float* __restrict__ B,
                   const float* __restrict__ bias, float* __restrict__ part,
                   long long sA, long long sB, int biasPerZ,
                   int Mvalid, int rowIsGlobal)
{
    extern __shared__ float sm[];
    float* bufA[2] = { sm,              sm + 2 * STAGEF };
    float* bufB[2] = { sm + STAGEF,     sm + 3 * STAGEF };

    int tid = threadIdx.x;
    int wid = tid >> 5;
    int lane = tid & 31;
    int q = lane >> 2;
    int t = lane & 3;
    int warpRow = (wid & 3) * 32;
    int warpCol = (wid >> 2) * 64;

    int rowBase = blockIdx.y * 128;
    int colBase = blockIdx.x * 128;
    long long z = blockIdx.z;
    const float* Arow = A + z * sA + (size_t)rowBase * D;
    const float* Brow = B + z * sB + (size_t)colBase * D;
    const float* biasp = bias + (biasPerZ ? z * (long long)D : 0) + colBase;

    float acc[2][8][4];
#pragma unroll
    for (int mt = 0; mt < 2; mt++)
#pragma unroll
        for (int nt = 0; nt < 8; nt++)
#pragma unroll
            for (int e = 0; e < 4; e++) acc[mt][nt][e] = 0.f;

    load_tile32(bufA[0], Arow, tid, 0);
    load_tile32(bufB[0], Brow, tid, 0);
    cpasync_commit();
    load_tile32(bufA[1], Arow, tid, 32);
    load_tile32(bufB[1], Brow, tid, 32);
    cpasync_commit();

    for (int kt = 0; kt < NKT; kt++) {
        int buf = kt & 1;
        if (kt < NKT - 2) asm volatile("cp.async.wait_group 1;" ::: "memory");
        else              asm volatile("cp.async.wait_group 0;" ::: "memory");
        __syncthreads();

        const float* As = bufA[buf];
        const float* Bs = bufB[buf];
#pragma unroll
        for (int ks = 0; ks < 4; ks++) {
            int k0 = ks * 8;
            float a[2][4];
#pragma unroll
            for (int mt = 0; mt < 2; mt++) {
                int r = warpRow + mt * 16 + q;
                a[mt][0] = As[(size_t)r * SSTRIDE + k0 + t];
                a[mt][1] = As[(size_t)(r + 8) * SSTRIDE + k0 + t];
                a[mt][2] = As[(size_t)r * SSTRIDE + k0 + t + 4];
                a[mt][3] = As[(size_t)(r + 8) * SSTRIDE + k0 + t + 4];
            }
            float b[8][2];
#pragma unroll
            for (int nt = 0; nt < 8; nt++) {
                int n = warpCol + nt * 8 + q;
                b[nt][0] = Bs[(size_t)n * SSTRIDE + k0 + t];
                b[nt][1] = Bs[(size_t)n * SSTRIDE + k0 + t + 4];
            }
#pragma unroll
            for (int mt = 0; mt < 2; mt++)
#pragma unroll
                for (int nt = 0; nt < 8; nt++)
                    mma16n8k8(acc[mt][nt], a[mt], b[nt]);
        }
        __syncthreads();

        if (kt + 2 < NKT) {
            int k0 = (kt + 2) * 32;
            load_tile32(bufA[buf], Arow, tid, k0);
            load_tile32(bufB[buf], Brow, tid, k0);
            cpasync_commit();
        }
    }

    // ---- epilogue: stage relu(D+bias)/196 into smem (masked rows) ----
    float* sD = sm;
    const float invR = 1.0f / (float)NPATCH;
#pragma unroll
    for (int mt = 0; mt < 2; mt++) {
        int r0 = warpRow + mt * 16 + q;
        int r1 = r0 + 8;
        bool v0 = (rowBase + r0) < Mvalid;
        bool v1 = (rowBase + r1) < Mvalid;
#pragma unroll
        for (int nt = 0; nt < 8; nt++) {
            int c = warpCol + nt * 8 + t * 2;
            float bv0 = biasp[c], bv1 = biasp[c + 1];
            float x0 = fmaxf(acc[mt][nt][0] + bv0, 0.f) * invR;
            float x1 = fmaxf(acc[mt][nt][1] + bv1, 0.f) * invR;
            float x2 = fmaxf(acc[mt][nt][2] + bv0, 0.f) * invR;
            float x3 = fmaxf(acc[mt][nt][3] + bv1, 0.f) * invR;
            sD[(size_t)r0 * 132 + c]     = v0 ? x0 : 0.f;
            sD[(size_t)r0 * 132 + c + 1] = v0 ? x1 : 0.f;
            sD[(size_t)r1 * 132 + c]     = v1 ? x2 : 0.f;
            sD[(size_t)r1 * 132 + c + 1] = v1 ? x3 : 0.f;
        }
    }
    __syncthreads();

    float* sRed = sm + SRED_OFF;
    {
        int col = tid & 127;
        int half = tid >> 7;
        int rbound = 128;
        if (rowIsGlobal) {
            int b0 = rowBase / NPATCH;
            rbound = (b0 + 1) * NPATCH - rowBase;
            if (rbound > 128) rbound = 128;
        }
        float a0 = 0.f, a1 = 0.f;
        int rs = half * 64;
        for (int r = rs; r < rs + 64; r++) {
            float v = sD[(size_t)r * 132 + col];
            if (r < rbound) a0 += v; else a1 += v;
        }
        sRed[(half * 2 + 0) * 128 + col] = a0;
        sRed[(half * 2 + 1) * 128 + col] = a1;
    }
    __syncthreads();
    if (tid < 128) {
        float s0 = sRed[0 * 128 + tid] + sRed[2 * 128 + tid];
        float s1 = sRed[1 * 128 + tid] + sRed[3 * 128 + tid];
        int col = colBase + tid;
        if (rowIsGlobal) {
            part[((size_t)blockIdx.y * 2 + 0) * D + col] = s0;
            part[((size_t)blockIdx.y * 2 + 1) * D + col] = s1;
        } else {
            part[((size_t)z * gridDim.y + blockIdx.y) * D + col] = s0;
        }
    }
}

// ---------------- combine pool partials ----------------
__global__ void combine1_kernel(const float* __restrict__ part, float* __restrict__ pooled)
{
    int idx = blockIdx.x * blockDim.x + threadIdx.x;
    if (idx >= BATCH * D) return;
    int j = idx % D;
    int b = idx / D;
    int r0 = (b * NPATCH) / 128;
    int r1 = (b * NPATCH + NPATCH - 1) / 128;
    float s = 0.f;
    for (int ry = r0; ry <= r1; ry++) {
        int tb = (ry * 128) / NPATCH;
        int slot = (b == tb) ? 0 : 1;
        s += part[((size_t)ry * 2 + slot) * D + j];
    }
    pooled[idx] = s;
}

__global__ void combine2_kernel(const float* __restrict__ part, float* __restrict__ pooled)
{
    int idx = blockIdx.x * blockDim.x + threadIdx.x;
    if (idx >= BATCH * D) return;
    int j = idx % D;
    int b = idx / D;
    pooled[idx] = part[((size_t)b * 2 + 0) * D + j] + part[((size_t)b * 2 + 1) * D + j];
}

// ---------------- patchify (float4, tf32-rounded) ----------------
__global__ void patchify4_kernel(const float* __restrict__ x, float4* __restrict__ out)
{
    int idx4 = blockIdx.x * blockDim.x + threadIdx.x;
    const int total4 = ROWS_TOT * (D / 4);
    if (idx4 >= total4) return;
    int d4 = idx4 % (D / 4);
    int rem = idx4 / (D / 4);
    int n = rem % NPATCH;
    int b = rem / NPATCH;
    int d = d4 * 4;
    int c = d >> 8;
    int r2 = d & 255;
    int i = r2 >> 4;
    int j = r2 & 15;
    int hp = n / 14;
    int wp = n % 14;
    int src = ((b * 3 + c) * 224 + hp * 16 + i) * 224 + wp * 16 + j;
    float4 v = *reinterpret_cast<const float4*>(x + src);
    v.x = rna_tf32(v.x); v.y = rna_tf32(v.y); v.z = rna_tf32(v.z); v.w = rna_tf32(v.w);
    out[idx4] = v;
}

// ---------------- transpose W1 / dW1 -> [N,K], tf32-rounded ----------------
__global__ void transpose_kernel(const float* __restrict__ W1, const float* __restrict__ dW1,
                                 float* __restrict__ W1T, float* __restrict__ dW1T)
{
    __shared__ float tile[32][33];
    int z = blockIdx.z;
    const float* src = (z == 0) ? W1 : dW1 + (size_t)(z - 1) * DD;
    float* dst = (z == 0) ? W1T : dW1T + (size_t)(z - 1) * DD;
    int xx = blockIdx.x * 32 + threadIdx.x;
    int y0 = blockIdx.y * 32;
    for (int i = threadIdx.y; i < 32; i += 8)
        tile[i][threadIdx.x] = src[(size_t)(y0 + i) * D + xx];
    __syncthreads();
    int ox = blockIdx.y * 32 + threadIdx.x;
    int oy0 = blockIdx.x * 32;
    for (int i = threadIdx.y; i < 32; i += 8)
        dst[(size_t)(oy0 + i) * D + ox] = rna_tf32(tile[threadIdx.x][i]);
}

// ---------------- Small GEMM (M=64) with split-K partials ----------------
#define SBK 32
__global__ __launch_bounds__(256)
void small_gemm(const float* __restrict__ A, const float* __restrict__ B0,
                const float* __restrict__ Bd, long long sB,
                float* __restrict__ part, int N, int Kc)
{
    int z = blockIdx.z;
    const float* B;
    if (B0) B = (z == 0) ? B0 : (Bd + (long long)(z - 1) * sB);
    else    B = Bd + (long long)z * sB;

    int S = gridDim.y;
    int sy = blockIdx.y;
    int colBase = blockIdx.x * 64;
    int k0 = sy * Kc;

    __shared__ float As[SBK][64];
    __shared__ float Bs[SBK][64];

    int tid = threadIdx.x;
    int tx = tid & 15;
    int ty = tid >> 4;

    float acc[4][4];
#pragma unroll
    for (int i = 0; i < 4; i++)
#pragma unroll
        for (int j = 0; j < 4; j++) acc[i][j] = 0.f;

    for (int kb = 0; kb < Kc; kb += SBK) {
#pragma unroll
        for (int u = 0; u < 2; u++) {
            int qq = tid + 256 * u;
            int row = qq >> 3;
            int kq = (qq & 7) * 4;
            float4 av = *reinterpret_cast<const float4*>(A + (long long)row * D + k0 + kb + kq);
            As[kq + 0][row] = av.x;
            As[kq + 1][row] = av.y;
            As[kq + 2][row] = av.z;
            As[kq + 3][row] = av.w;
        }
#pragma unroll
        for (int u = 0; u < 2; u++) {
            int qq = tid + 256 * u;
            int k = qq >> 4;
            int col4 = (qq & 15) * 4;
            *reinterpret_cast<float4*>(&Bs[k][col4]) =
                *reinterpret_cast<const float4*>(B + (long long)(k0 + kb + k) * N + colBase + col4);
        }
        __syncthreads();
#pragma unroll
        for (int k = 0; k < SBK; k++) {
            float4 a4 = *reinterpret_cast<const float4*>(&As[k][ty * 4]);
            float4 b4 = *reinterpret_cast<const float4*>(&Bs[k][tx * 4]);
            float ra[4] = {a4.x, a4.y, a4.z, a4.w};
            float rb[4] = {b4.x, b4.y, b4.z, b4.w};
#pragma unroll
            for (int i = 0; i < 4; i++)
#pragma unroll
                for (int j = 0; j < 4; j++)
                    acc[i][j] = fmaf(ra[i], rb[j], acc[i][j]);
        }
        __syncthreads();
    }

    float* dst = part + ((long long)(z * S + sy) * 64) * N;
#pragma unroll
    for (int i = 0; i < 4; i++) {
        int r = ty * 4 + i;
        *reinterpret_cast<float4*>(dst + (long long)r * N + colBase + tx * 4) =
            make_float4(acc[i][0], acc[i][1], acc[i][2], acc[i][3]);
    }
}

__global__ void reduce_kernel(const float* __restrict__ part, float* __restrict__ dst,
                              const float* __restrict__ bias, int N, int relu)
{
    int idx = blockIdx.x * blockDim.x + threadIdx.x;
    if (idx >= BATCH * N) return;
    float v = bias ? bias[idx % N] : 0.f;
#pragma unroll
    for (int s = 0; s < SPLITS; s++) v += part[(long long)s * BATCH * N + idx];
    if (relu) v = fmaxf(v, 0.f);
    dst[idx] = v;
}

__global__ void coefs_kernel(const float* __restrict__ mw2, const float* __restrict__ mb2)
{
    int t = threadIdx.x;
    int b = t >> 3;
    int j = t & 7;
    float s = mb2[j];
    for (int k = 0; k < HMETA; k++)
        s = fmaf(g_hid[b * HMETA + k], mw2[k * T + j], s);
    g_coefs[b * T + j] = s;
}

__global__ void mixbias_kernel(const float* __restrict__ b1, const float* __restrict__ db1,
                               const float* __restrict__ b2, const float* __restrict__ db2)
{
    int idx = blockIdx.x * blockDim.x + threadIdx.x;
    if (idx >= BATCH * D) return;
    int j = idx % D;
    int b = idx / D;
    float c[T];
#pragma unroll
    for (int t = 0; t < T; t++) c[t] = g_coefs[b * T + t];
    float v1 = b1[j], v2 = b2[j];
#pragma unroll
    for (int t = 0; t < T; t++) {
        v1 = fmaf(c[t], db1[t * D + j], v1);
        v2 = fmaf(c[t], db2[t * D + j], v2);
    }
    g_nb1[idx] = v1;
    g_nb2[idx] = v2;
}

// ---------------- mixW1T: batch-in-registers version ----------------
// One thread owns one float4 weight position r. Loads W1T[r] + 8 dW1T[t][r]
// into registers ONCE (36 floats), then streams all 64 batches:
// 8 broadcast-LDS coefs + 32 FMA + 1 coalesced STG.128 per batch.
// L2/DRAM traffic: 21 MB read + 151 MB write (vs 1.36 GB read before).
__global__ __launch_bounds__(256)
void mixw1t_kernel(void)
{
    __shared__ float sc[BATCH * T];   // 2 KB
    int tid = threadIdx.x;
    // 512 coefs, 256 threads -> 2 each (float2)
    reinterpret_cast<float2*>(sc)[tid] = reinterpret_cast<const float2*>(g_coefs)[tid];
    __syncthreads();

    const long long per_b4 = DD / 4;                        // 147456
    long long r = (long long)blockIdx.x * 256 + tid;        // < per_b4 (576 blocks)

    float4 w = reinterpret_cast<const float4*>(g_W1T)[r];
    float4 dv[T];
#pragma unroll
    for (int t = 0; t < T; t++)
        dv[t] = reinterpret_cast<const float4*>(g_dW1T)[(long long)t * per_b4 + r];

    float4* outp = reinterpret_cast<float4*>(g_mixW1T) + r;
#pragma unroll 4
    for (int b = 0; b < BATCH; b++) {
        float4 v = w;
#pragma unroll
        for (int t = 0; t < T; t++) {
            float c = sc[b * T + t];          // broadcast, conflict-free
            v.x = fmaf(c, dv[t].x, v.x);
            v.y = fmaf(c, dv[t].y, v.y);
            v.z = fmaf(c, dv[t].z, v.z);
            v.w = fmaf(c, dv[t].w, v.w);
        }
        v.x = rna_tf32(v.x); v.y = rna_tf32(v.y);
        v.z = rna_tf32(v.z); v.w = rna_tf32(v.w);
        outp[(long long)b * per_b4] = v;
    }
}

__global__ void final_out_kernel(const float* __restrict__ part, float* __restrict__ out)
{
    int idx = blockIdx.x * blockDim.x + threadIdx.x;
    if (idx >= BATCH * D) return;
    int b = idx / D;
    const int SLAB = BATCH * D;
    float v = g_nb2[idx];
#pragma unroll
    for (int s = 0; s < SPLITS; s++) v += part[(long long)s * SLAB + idx];
#pragma unroll
    for (int t = 0; t < T; t++) {
        float qv = 0.f;
#pragma unroll
        for (int s = 0; s < SPLITS; s++)
            qv += part[(long long)((t + 1) * SPLITS + s) * SLAB + idx];
        v = fmaf(g_coefs[b * T + t], qv, v);
    }
    out[idx] = v;
}

// ---------------- launch ----------------
extern "C" void kernel_launch(void* const* d_in, const int* in_sizes, int n_in,
                              void* d_out, int out_size)
{
    const float* x   = (const float*)d_in[0];
    const float* W1  = (const float*)d_in[1];
    const float* b1  = (const float*)d_in[2];
    const float* W2  = (const float*)d_in[3];
    const float* b2  = (const float*)d_in[4];
    const float* dW1 = (const float*)d_in[5];
    const float* db1 = (const float*)d_in[6];
    const float* dW2 = (const float*)d_in[7];
    const float* db2 = (const float*)d_in[8];
    const float* mw1 = (const float*)d_in[9];
    const float* mb1 = (const float*)d_in[10];
    const float* mw2 = (const float*)d_in[11];
    const float* mb2 = (const float*)d_in[12];
    float* out = (float*)d_out;

    float *patches, *W1T, *dW1T, *mixW1T, *pooled, *pooled2, *base, *hid;
    float *part, *p1part, *p2part, *nb1;
    cudaGetSymbolAddress((void**)&patches, g_patches);
    cudaGetSymbolAddress((void**)&W1T,     g_W1T);
    cudaGetSymbolAddress((void**)&dW1T,    g_dW1T);
    cudaGetSymbolAddress((void**)&mixW1T,  g_mixW1T);
    cudaGetSymbolAddress((void**)&pooled,  g_pooled);
    cudaGetSymbolAddress((void**)&pooled2, g_pooled2);
    cudaGetSymbolAddress((void**)&base,    g_base);
    cudaGetSymbolAddress((void**)&hid,     g_hid);
    cudaGetSymbolAddress((void**)&part,    g_part);
    cudaGetSymbolAddress((void**)&p1part,  g_p1part);
    cudaGetSymbolAddress((void**)&p2part,  g_p2part);
    cudaGetSymbolAddress((void**)&nb1,     g_nb1);

    cudaFuncSetAttribute(mma_gemm_pool, cudaFuncAttributeMaxDynamicSharedMemorySize, SM_BYTES);

    const int TPB = 256;

    // 1) patchify (tf32-rounded)
    {
        int total4 = ROWS_TOT * (D / 4);
        patchify4_kernel<<<(total4 + TPB - 1) / TPB, TPB>>>(x, (float4*)patches);
    }

    // 2) transpose W1 -> W1T, dW1 -> dW1T (tf32-rounded)
    transpose_kernel<<<dim3(D / 32, D / 32, T + 1), dim3(32, 8)>>>(W1, dW1, W1T, dW1T);

    // 3) GEMM1 (mma.sync tf32) fused relu+pool partials
    mma_gemm_pool<<<dim3(D / 128, ROWTILES1, 1), 256, SM_BYTES>>>(
        patches, W1T, b1, p1part, 0, 0, 0, ROWS_TOT, 1);
    combine1_kernel<<<(BATCH * D + TPB - 1) / TPB, TPB>>>(p1part, pooled);

    // 4) base = pooled @ W2 + b2
    small_gemm<<<dim3(D / 64, SPLITS, 1), 256>>>(pooled, W2, nullptr, 0, part, D, D / SPLITS);
    reduce_kernel<<<(BATCH * D + TPB - 1) / TPB, TPB>>>(part, base, b2, D, 0);

    // 5) hid = relu(base @ mw1 + mb1)
    small_gemm<<<dim3(HMETA / 64, SPLITS, 1), 256>>>(base, mw1, nullptr, 0, part, HMETA, D / SPLITS);
    reduce_kernel<<<(BATCH * HMETA + TPB - 1) / TPB, TPB>>>(part, hid, mb1, HMETA, 1);

    // 6) coefs
    coefs_kernel<<<1, 512>>>(mw2, mb2);

    // 7) mixed biases
    mixbias_kernel<<<(BATCH * D + TPB - 1) / TPB, TPB>>>(b1, db1, b2, db2);

    // 8) mixW1T (batch-in-registers, tf32-rounded)
    mixw1t_kernel<<<DD / 4 / 256, 256>>>();

    // 9) GEMM2 (mma.sync tf32, batched) fused relu+pool partials
    mma_gemm_pool<<<dim3(D / 128, 2, BATCH), 256, SM_BYTES>>>(
        patches, mixW1T, nb1, p2part,
        (long long)NPATCH * D, (long long)DD, 1, NPATCH, 0);
    combine2_kernel<<<(BATCH * D + TPB - 1) / TPB, TPB>>>(p2part, pooled2);

    // 10+11) q (dW2 tasks) + W2 head via z=0 (split-K partials)
    small_gemm<<<dim3(D / 64, SPLITS, T + 1), 256>>>(pooled2, W2, dW2, (long long)DD, part, D, D / SPLITS);

    // 12) final output
    final_out_kernel<<<(BATCH * D + TPB - 1) / TPB, TPB>>>(part, out);
}

// round 7
// speedup vs baseline: 6.1536x; 1.4580x over previous
#include <cuda_runtime.h>
#include <cuda_bf16.h>
#include <cstdint>

// ---------------- Problem constants ----------------
#define BATCH 64
#define NPATCH 196
#define D 768
#define T 8
#define HMETA 192
#define ROWS_TOT (BATCH * NPATCH)   // 12544
#define DD (D * D)
#define SPLITS 6
#define KC 64                        // K-chunk (bf16)
#define NKT 12                       // 768 / 64
#define ROWTILES1 98                 // 12544 / 128

// ---------------- Device scratch ----------------
__device__ __nv_bfloat16 g_patchesH[(size_t)(ROWS_TOT + 64) * D];   // 19.3 MB (+pad rows zero)
__device__ __nv_bfloat16 g_W1TH[DD];
__device__ __nv_bfloat16 g_dW1TH[(size_t)T * DD];
__device__ __nv_bfloat16 g_mixW1TH[(size_t)BATCH * DD];             // 75 MB
__device__ float g_pooled[BATCH * D];
__device__ float g_pooled2[BATCH * D];
__device__ float g_base[BATCH * D];
__device__ float g_hid[BATCH * HMETA];
__device__ float g_coefs[BATCH * T];
__device__ float g_nb1[BATCH * D];
__device__ float g_nb2[BATCH * D];
__device__ float g_part[(size_t)(T + 1) * SPLITS * BATCH * D];
__device__ float g_p1part[(size_t)ROWTILES1 * 2 * D];
__device__ float g_p2part[(size_t)BATCH * 2 * D];

// ---------------- PTX helpers (sm_80 baseline) ----------------
__device__ __forceinline__ void cpasync16(uint32_t dst, const void* src) {
    asm volatile("cp.async.cg.shared.global [%0], [%1], 16;" :: "r"(dst), "l"(src));
}
__device__ __forceinline__ void cpasync_commit() {
    asm volatile("cp.async.commit_group;" ::: "memory");
}
__device__ __forceinline__ void mma_bf16(float* c, const uint32_t* a, const uint32_t* b) {
    asm volatile("mma.sync.aligned.m16n8k16.row.col.f32.bf16.bf16.f32 "
        "{%0,%1,%2,%3}, {%4,%5,%6,%7}, {%8,%9}, {%0,%1,%2,%3};"
        : "+f"(c[0]), "+f"(c[1]), "+f"(c[2]), "+f"(c[3])
        : "r"(a[0]), "r"(a[1]), "r"(a[2]), "r"(a[3]), "r"(b[0]), "r"(b[1]));
}
__device__ __forceinline__ uint32_t packbf2(float lo, float hi) {
    __nv_bfloat162 p = __floats2bfloat162_rn(lo, hi);
    return *reinterpret_cast<uint32_t*>(&p);
}

// ---------------- SMEM layout for mma_gemm_pool ----------------
// 4 buffers of 128 x 72 halves (64 data + 8 pad). 144B row stride = 16B-aligned,
// row-to-row bank offset = 4 -> fragment loads (bank q*4+t) hit 32 distinct banks.
#define HSTRIDE 72
#define STAGEH (128 * HSTRIDE)            // 9216 halves = 18432 bytes
#define SM_BYTES (4 * STAGEH * 2)         // 73728 bytes
#define SRED_OFF (128 * 132)              // float offset for reduction scratch

// load one 128x64 bf16 tile (row-major, ld = D halves) into smem [128][72]
__device__ __forceinline__ void load_tile64(__nv_bfloat16* dstBase,
                                            const __nv_bfloat16* src,
                                            int tid, int k0)
{
#pragma unroll
    for (int u = 0; u < 4; u++) {
        int q = tid + 256 * u;          // 0..1023
        int row = q >> 3;
        int c8 = (q & 7) * 8;           // halves
        uint32_t dst = (uint32_t)__cvta_generic_to_shared(dstBase + row * HSTRIDE + c8);
        cpasync16(dst, src + (size_t)row * D + k0 + c8);
    }
}

// ---------------- bf16 mma GEMM + fused relu + mean-pool partials ----------------
// D_tile = A[128xK] @ B_tile^T (B stored [N,K] K-major, bf16).
// Epilogue: relu(D + bias) / 196, column-summed into per-tile partials (fp32).
__global__ __launch_bounds__(256, 2)
void mma_gemm_pool(const __nv_bfloat16* __restrict__ A, const __nv_bfloat16* __restrict__ B,
                   const float* __restrict__ bias, float* __restrict__ part,
                   long long sA, long long sB, int biasPerZ,
                   int Mvalid, int rowIsGlobal)
{
    extern __shared__ __nv_bfloat16 smh[];
    __nv_bfloat16* bufA[2] = { smh,              smh + 2 * STAGEH };
    __nv_bfloat16* bufB[2] = { smh + STAGEH,     smh + 3 * STAGEH };

    int tid = threadIdx.x;
    int wid = tid >> 5;
    int lane = tid & 31;
    int q = lane >> 2;      // 0..7
    int t = lane & 3;       // 0..3
    int warpRow = (wid & 3) * 32;
    int warpCol = (wid >> 2) * 64;

    int rowBase = blockIdx.y * 128;
    int colBase = blockIdx.x * 128;
    long long z = blockIdx.z;
    const __nv_bfloat16* Arow = A + z * sA + (size_t)rowBase * D;
    const __nv_bfloat16* Brow = B + z * sB + (size_t)colBase * D;
    const float* biasp = bias + (biasPerZ ? z * (long long)D : 0) + colBase;

    float acc[2][8][4];
#pragma unroll
    for (int mt = 0; mt < 2; mt++)
#pragma unroll
        for (int nt = 0; nt < 8; nt++)
#pragma unroll
            for (int e = 0; e < 4; e++) acc[mt][nt][e] = 0.f;

    load_tile64(bufA[0], Arow, tid, 0);
    load_tile64(bufB[0], Brow, tid, 0);
    cpasync_commit();
    load_tile64(bufA[1], Arow, tid, KC);
    load_tile64(bufB[1], Brow, tid, KC);
    cpasync_commit();

    for (int kt = 0; kt < NKT; kt++) {
        int buf = kt & 1;
        if (kt < NKT - 2) asm volatile("cp.async.wait_group 1;" ::: "memory");
        else              asm volatile("cp.async.wait_group 0;" ::: "memory");
        __syncthreads();

        const __nv_bfloat16* As = bufA[buf];
        const __nv_bfloat16* Bs = bufB[buf];
#pragma unroll
        for (int ks = 0; ks < 4; ks++) {
            int k0 = ks * 16;
            uint32_t a[2][4];
#pragma unroll
            for (int mt = 0; mt < 2; mt++) {
                int r = warpRow + mt * 16 + q;
                a[mt][0] = *reinterpret_cast<const uint32_t*>(&As[(size_t)r * HSTRIDE + k0 + 2 * t]);
                a[mt][1] = *reinterpret_cast<const uint32_t*>(&As[(size_t)(r + 8) * HSTRIDE + k0 + 2 * t]);
                a[mt][2] = *reinterpret_cast<const uint32_t*>(&As[(size_t)r * HSTRIDE + k0 + 2 * t + 8]);
                a[mt][3] = *reinterpret_cast<const uint32_t*>(&As[(size_t)(r + 8) * HSTRIDE + k0 + 2 * t + 8]);
            }
            uint32_t b[8][2];
#pragma unroll
            for (int nt = 0; nt < 8; nt++) {
                int n = warpCol + nt * 8 + q;
                b[nt][0] = *reinterpret_cast<const uint32_t*>(&Bs[(size_t)n * HSTRIDE + k0 + 2 * t]);
                b[nt][1] = *reinterpret_cast<const uint32_t*>(&Bs[(size_t)n * HSTRIDE + k0 + 2 * t + 8]);
            }
#pragma unroll
            for (int mt = 0; mt < 2; mt++)
#pragma unroll
                for (int nt = 0; nt < 8; nt++)
                    mma_bf16(acc[mt][nt], a[mt], b[nt]);
        }
        __syncthreads();

        if (kt + 2 < NKT) {
            int k0 = (kt + 2) * KC;
            load_tile64(bufA[buf], Arow, tid, k0);
            load_tile64(bufB[buf], Brow, tid, k0);
            cpasync_commit();
        }
    }

    // ---- epilogue: stage relu(D+bias)/196 into smem (masked rows) ----
    float* sD = reinterpret_cast<float*>(smh);   // 128 x 132 fp32
    const float invR = 1.0f / (float)NPATCH;
#pragma unroll
    for (int mt = 0; mt < 2; mt++) {
        int r0 = warpRow + mt * 16 + q;
        int r1 = r0 + 8;
        bool v0 = (rowBase + r0) < Mvalid;
        bool v1 = (rowBase + r1) < Mvalid;
#pragma unroll
        for (int nt = 0; nt < 8; nt++) {
            int c = warpCol + nt * 8 + t * 2;
            float bv0 = biasp[c], bv1 = biasp[c + 1];
            float x0 = fmaxf(acc[mt][nt][0] + bv0, 0.f) * invR;
            float x1 = fmaxf(acc[mt][nt][1] + bv1, 0.f) * invR;
            float x2 = fmaxf(acc[mt][nt][2] + bv0, 0.f) * invR;
            float x3 = fmaxf(acc[mt][nt][3] + bv1, 0.f) * invR;
            sD[(size_t)r0 * 132 + c]     = v0 ? x0 : 0.f;
            sD[(size_t)r0 * 132 + c + 1] = v0 ? x1 : 0.f;
            sD[(size_t)r1 * 132 + c]     = v1 ? x2 : 0.f;
            sD[(size_t)r1 * 132 + c + 1] = v1 ? x3 : 0.f;
        }
    }
    __syncthreads();

    // ---- two-phase deterministic column reduction ----
    float* sRed = reinterpret_cast<float*>(smh) + SRED_OFF;
    {
        int col = tid & 127;
        int half = tid >> 7;
        int rbound = 128;
        if (rowIsGlobal) {
            int b0 = rowBase / NPATCH;
            rbound = (b0 + 1) * NPATCH - rowBase;
            if (rbound > 128) rbound = 128;
        }
        float a0 = 0.f, a1 = 0.f;
        int rs = half * 64;
        for (int r = rs; r < rs + 64; r++) {
            float v = sD[(size_t)r * 132 + col];
            if (r < rbound) a0 += v; else a1 += v;
        }
        sRed[(half * 2 + 0) * 128 + col] = a0;
        sRed[(half * 2 + 1) * 128 + col] = a1;
    }
    __syncthreads();
    if (tid < 128) {
        float s0 = sRed[0 * 128 + tid] + sRed[2 * 128 + tid];
        float s1 = sRed[1 * 128 + tid] + sRed[3 * 128 + tid];
        int col = colBase + tid;
        if (rowIsGlobal) {
            part[((size_t)blockIdx.y * 2 + 0) * D + col] = s0;
            part[((size_t)blockIdx.y * 2 + 1) * D + col] = s1;
        } else {
            part[((size_t)z * gridDim.y + blockIdx.y) * D + col] = s0;
        }
    }
}

// ---------------- combine pool partials ----------------
__global__ void combine1_kernel(const float* __restrict__ part, float* __restrict__ pooled)
{
    int idx = blockIdx.x * blockDim.x + threadIdx.x;
    if (idx >= BATCH * D) return;
    int j = idx % D;
    int b = idx / D;
    int r0 = (b * NPATCH) / 128;
    int r1 = (b * NPATCH + NPATCH - 1) / 128;
    float s = 0.f;
    for (int ry = r0; ry <= r1; ry++) {
        int tb = (ry * 128) / NPATCH;
        int slot = (b == tb) ? 0 : 1;
        s += part[((size_t)ry * 2 + slot) * D + j];
    }
    pooled[idx] = s;
}

__global__ void combine2_kernel(const float* __restrict__ part, float* __restrict__ pooled)
{
    int idx = blockIdx.x * blockDim.x + threadIdx.x;
    if (idx >= BATCH * D) return;
    int j = idx % D;
    int b = idx / D;
    pooled[idx] = part[((size_t)b * 2 + 0) * D + j] + part[((size_t)b * 2 + 1) * D + j];
}

// ---------------- patchify -> bf16 ----------------
__global__ void patchify4_kernel(const float* __restrict__ x, uint2* __restrict__ outH)
{
    int idx4 = blockIdx.x * blockDim.x + threadIdx.x;
    const int total4 = ROWS_TOT * (D / 4);
    if (idx4 >= total4) return;
    int d4 = idx4 % (D / 4);
    int rem = idx4 / (D / 4);
    int n = rem % NPATCH;
    int b = rem / NPATCH;
    int d = d4 * 4;
    int c = d >> 8;
    int r2 = d & 255;
    int i = r2 >> 4;
    int j = r2 & 15;
    int hp = n / 14;
    int wp = n % 14;
    int src = ((b * 3 + c) * 224 + hp * 16 + i) * 224 + wp * 16 + j;
    float4 v = *reinterpret_cast<const float4*>(x + src);
    uint2 o;
    o.x = packbf2(v.x, v.y);
    o.y = packbf2(v.z, v.w);
    outH[idx4] = o;
}

// ---------------- transpose W1 / dW1 -> [N,K] bf16 ----------------
__global__ void transpose_kernel(const float* __restrict__ W1, const float* __restrict__ dW1,
                                 __nv_bfloat16* __restrict__ W1TH,
                                 __nv_bfloat16* __restrict__ dW1TH)
{
    __shared__ float tile[32][33];
    int z = blockIdx.z;
    const float* src = (z == 0) ? W1 : dW1 + (size_t)(z - 1) * DD;
    __nv_bfloat16* dst = (z == 0) ? W1TH : dW1TH + (size_t)(z - 1) * DD;
    int xx = blockIdx.x * 32 + threadIdx.x;
    int y0 = blockIdx.y * 32;
    for (int i = threadIdx.y; i < 32; i += 8)
        tile[i][threadIdx.x] = src[(size_t)(y0 + i) * D + xx];
    __syncthreads();
    int ox = blockIdx.y * 32 + threadIdx.x;
    int oy0 = blockIdx.x * 32;
    for (int i = threadIdx.y; i < 32; i += 8)
        dst[(size_t)(oy0 + i) * D + ox] = __float2bfloat16_rn(tile[threadIdx.x][i]);
}

// ---------------- Small GEMM (M=64, fp32) with split-K partials ----------------
#define SBK 32
__global__ __launch_bounds__(256)
void small_gemm(const float* __restrict__ A, const float* __restrict__ B0,
                const float* __restrict__ Bd, long long sB,
                float* __restrict__ part, int N, int Kc)
{
    int z = blockIdx.z;
    const float* B;
    if (B0) B = (z == 0) ? B0 : (Bd + (long long)(z - 1) * sB);
    else    B = Bd + (long long)z * sB;

    int S = gridDim.y;
    int sy = blockIdx.y;
    int colBase = blockIdx.x * 64;
    int k0 = sy * Kc;

    __shared__ float As[SBK][64];
    __shared__ float Bs[SBK][64];

    int tid = threadIdx.x;
    int tx = tid & 15;
    int ty = tid >> 4;

    float acc[4][4];
#pragma unroll
    for (int i = 0; i < 4; i++)
#pragma unroll
        for (int j = 0; j < 4; j++) acc[i][j] = 0.f;

    for (int kb = 0; kb < Kc; kb += SBK) {
#pragma unroll
        for (int u = 0; u < 2; u++) {
            int qq = tid + 256 * u;
            int row = qq >> 3;
            int kq = (qq & 7) * 4;
            float4 av = *reinterpret_cast<const float4*>(A + (long long)row * D + k0 + kb + kq);
            As[kq + 0][row] = av.x;
            As[kq + 1][row] = av.y;
            As[kq + 2][row] = av.z;
            As[kq + 3][row] = av.w;
        }
#pragma unroll
        for (int u = 0; u < 2; u++) {
            int qq = tid + 256 * u;
            int k = qq >> 4;
            int col4 = (qq & 15) * 4;
            *reinterpret_cast<float4*>(&Bs[k][col4]) =
                *reinterpret_cast<const float4*>(B + (long long)(k0 + kb + k) * N + colBase + col4);
        }
        __syncthreads();
#pragma unroll
        for (int k = 0; k < SBK; k++) {
            float4 a4 = *reinterpret_cast<const float4*>(&As[k][ty * 4]);
            float4 b4 = *reinterpret_cast<const float4*>(&Bs[k][tx * 4]);
            float ra[4] = {a4.x, a4.y, a4.z, a4.w};
            float rb[4] = {b4.x, b4.y, b4.z, b4.w};
#pragma unroll
            for (int i = 0; i < 4; i++)
#pragma unroll
                for (int j = 0; j < 4; j++)
                    acc[i][j] = fmaf(ra[i], rb[j], acc[i][j]);
        }
        __syncthreads();
    }

    float* dst = part + ((long long)(z * S + sy) * 64) * N;
#pragma unroll
    for (int i = 0; i < 4; i++) {
        int r = ty * 4 + i;
        *reinterpret_cast<float4*>(dst + (long long)r * N + colBase + tx * 4) =
            make_float4(acc[i][0], acc[i][1], acc[i][2], acc[i][3]);
    }
}

__global__ void reduce_kernel(const float* __restrict__ part, float* __restrict__ dst,
                              const float* __restrict__ bias, int N, int relu)
{
    int idx = blockIdx.x * blockDim.x + threadIdx.x;
    if (idx >= BATCH * N) return;
    float v = bias ? bias[idx % N] : 0.f;
#pragma unroll
    for (int s = 0; s < SPLITS; s++) v += part[(long long)s * BATCH * N + idx];
    if (relu) v = fmaxf(v, 0.f);
    dst[idx] = v;
}

__global__ void coefs_kernel(const float* __restrict__ mw2, const float* __restrict__ mb2)
{
    int t = threadIdx.x;
    int b = t >> 3;
    int j = t & 7;
    float s = mb2[j];
    for (int k = 0; k < HMETA; k++)
        s = fmaf(g_hid[b * HMETA + k], mw2[k * T + j], s);
    g_coefs[b * T + j] = s;
}

__global__ void mixbias_kernel(const float* __restrict__ b1, const float* __restrict__ db1,
                               const float* __restrict__ b2, const float* __restrict__ db2)
{
    int idx = blockIdx.x * blockDim.x + threadIdx.x;
    if (idx >= BATCH * D) return;
    int j = idx % D;
    int b = idx / D;
    float c[T];
#pragma unroll
    for (int t = 0; t < T; t++) c[t] = g_coefs[b * T + t];
    float v1 = b1[j], v2 = b2[j];
#pragma unroll
    for (int t = 0; t < T; t++) {
        v1 = fmaf(c[t], db1[t * D + j], v1);
        v2 = fmaf(c[t], db2[t * D + j], v2);
    }
    g_nb1[idx] = v1;
    g_nb2[idx] = v2;
}

// ---------------- mixW1TH: batch-in-registers, bf16 in/out ----------------
// Thread owns 4 halves at position r (uint2). Loads W1TH[r] + 8 dW1TH[t][r]
// once (36 fp32 regs), then streams 64 batches: 8 broadcast-LDS coefs,
// 16 FMA, 1 coalesced 8B store each.
__global__ __launch_bounds__(256)
void mixw1t_kernel(void)
{
    __shared__ float sc[BATCH * T];
    int tid = threadIdx.x;
    reinterpret_cast<float2*>(sc)[tid] = reinterpret_cast<const float2*>(g_coefs)[tid];
    __syncthreads();

    const long long per_b4 = DD / 4;                         // uint2 positions per batch
    long long r = (long long)blockIdx.x * 256 + tid;         // < per_b4 (576 blocks)

    const __nv_bfloat162* w2p = reinterpret_cast<const __nv_bfloat162*>(g_W1TH);
    float w[4];
    {
        float2 lo = __bfloat1622float2(w2p[2 * r]);
        float2 hi = __bfloat1622float2(w2p[2 * r + 1]);
        w[0] = lo.x; w[1] = lo.y; w[2] = hi.x; w[3] = hi.y;
    }
    float dv[T][4];
#pragma unroll
    for (int t = 0; t < T; t++) {
        const __nv_bfloat162* dp =
            reinterpret_cast<const __nv_bfloat162*>(g_dW1TH + (size_t)t * DD);
        float2 lo = __bfloat1622float2(dp[2 * r]);
        float2 hi = __bfloat1622float2(dp[2 * r + 1]);
        dv[t][0] = lo.x; dv[t][1] = lo.y; dv[t][2] = hi.x; dv[t][3] = hi.y;
    }

    uint2* outp = reinterpret_cast<uint2*>(g_mixW1TH) + r;
#pragma unroll 4
    for (int b = 0; b < BATCH; b++) {
        float v0 = w[0], v1 = w[1], v2 = w[2], v3 = w[3];
#pragma unroll
        for (int t = 0; t < T; t++) {
            float c = sc[b * T + t];
            v0 = fmaf(c, dv[t][0], v0);
            v1 = fmaf(c, dv[t][1], v1);
            v2 = fmaf(c, dv[t][2], v2);
            v3 = fmaf(c, dv[t][3], v3);
        }
        uint2 o;
        o.x = packbf2(v0, v1);
        o.y = packbf2(v2, v3);
        outp[(long long)b * per_b4] = o;
    }
}

__global__ void final_out_kernel(const float* __restrict__ part, float* __restrict__ out)
{
    int idx = blockIdx.x * blockDim.x + threadIdx.x;
    if (idx >= BATCH * D) return;
    int b = idx / D;
    const int SLAB = BATCH * D;
    float v = g_nb2[idx];
#pragma unroll
    for (int s = 0; s < SPLITS; s++) v += part[(long long)s * SLAB + idx];
#pragma unroll
    for (int t = 0; t < T; t++) {
        float qv = 0.f;
#pragma unroll
        for (int s = 0; s < SPLITS; s++)
            qv += part[(long long)((t + 1) * SPLITS + s) * SLAB + idx];
        v = fmaf(g_coefs[b * T + t], qv, v);
    }
    out[idx] = v;
}

// ---------------- launch ----------------
extern "C" void kernel_launch(void* const* d_in, const int* in_sizes, int n_in,
                              void* d_out, int out_size)
{
    const float* x   = (const float*)d_in[0];
    const float* W1  = (const float*)d_in[1];
    const float* b1  = (const float*)d_in[2];
    const float* W2  = (const float*)d_in[3];
    const float* b2  = (const float*)d_in[4];
    const float* dW1 = (const float*)d_in[5];
    const float* db1 = (const float*)d_in[6];
    const float* dW2 = (const float*)d_in[7];
    const float* db2 = (const float*)d_in[8];
    const float* mw1 = (const float*)d_in[9];
    const float* mb1 = (const float*)d_in[10];
    const float* mw2 = (const float*)d_in[11];
    const float* mb2 = (const float*)d_in[12];
    float* out = (float*)d_out;

    __nv_bfloat16 *patchesH, *W1TH, *dW1TH, *mixW1TH;
    float *pooled, *pooled2, *base, *hid, *part, *p1part, *p2part, *nb1;
    cudaGetSymbolAddress((void**)&patchesH, g_patchesH);
    cudaGetSymbolAddress((void**)&W1TH,     g_W1TH);
    cudaGetSymbolAddress((void**)&dW1TH,    g_dW1TH);
    cudaGetSymbolAddress((void**)&mixW1TH,  g_mixW1TH);
    cudaGetSymbolAddress((void**)&pooled,   g_pooled);
    cudaGetSymbolAddress((void**)&pooled2,  g_pooled2);
    cudaGetSymbolAddress((void**)&base,     g_base);
    cudaGetSymbolAddress((void**)&hid,      g_hid);
    cudaGetSymbolAddress((void**)&part,     g_part);
    cudaGetSymbolAddress((void**)&p1part,   g_p1part);
    cudaGetSymbolAddress((void**)&p2part,   g_p2part);
    cudaGetSymbolAddress((void**)&nb1,      g_nb1);

    cudaFuncSetAttribute(mma_gemm_pool, cudaFuncAttributeMaxDynamicSharedMemorySize, SM_BYTES);

    const int TPB = 256;

    // 1) patchify -> bf16
    {
        int total4 = ROWS_TOT * (D / 4);
        patchify4_kernel<<<(total4 + TPB - 1) / TPB, TPB>>>(x, (uint2*)patchesH);
    }

    // 2) transpose W1 -> W1TH, dW1 -> dW1TH (bf16)
    transpose_kernel<<<dim3(D / 32, D / 32, T + 1), dim3(32, 8)>>>(W1, dW1, W1TH, dW1TH);

    // 3) GEMM1 (bf16 mma) fused relu+pool partials
    mma_gemm_pool<<<dim3(D / 128, ROWTILES1, 1), 256, SM_BYTES>>>(
        patchesH, W1TH, b1, p1part, 0, 0, 0, ROWS_TOT, 1);
    combine1_kernel<<<(BATCH * D + TPB - 1) / TPB, TPB>>>(p1part, pooled);

    // 4) base = pooled @ W2 + b2
    small_gemm<<<dim3(D / 64, SPLITS, 1), 256>>>(pooled, W2, nullptr, 0, part, D, D / SPLITS);
    reduce_kernel<<<(BATCH * D + TPB - 1) / TPB, TPB>>>(part, base, b2, D, 0);

    // 5) hid = relu(base @ mw1 + mb1)
    small_gemm<<<dim3(HMETA / 64, SPLITS, 1), 256>>>(base, mw1, nullptr, 0, part, HMETA, D / SPLITS);
    reduce_kernel<<<(BATCH * HMETA + TPB - 1) / TPB, TPB>>>(part, hid, mb1, HMETA, 1);

    // 6) coefs
    coefs_kernel<<<1, 512>>>(mw2, mb2);

    // 7) mixed biases
    mixbias_kernel<<<(BATCH * D + TPB - 1) / TPB, TPB>>>(b1, db1, b2, db2);

    // 8) mixW1TH (batch-in-registers, bf16)
    mixw1t_kernel<<<DD / 4 / 256, 256>>>();

    // 9) GEMM2 (bf16 mma, batched) fused relu+pool partials
    mma_gemm_pool<<<dim3(D / 128, 2, BATCH), 256, SM_BYTES>>>(
        patchesH, mixW1TH, nb1, p2part,
        (long long)NPATCH * D, (long long)DD, 1, NPATCH, 0);
    combine2_kernel<<<(BATCH * D + TPB - 1) / TPB, TPB>>>(p2part, pooled2);

    // 10+11) q (dW2 tasks) + W2 head via z=0 (split-K partials)
    small_gemm<<<dim3(D / 64, SPLITS, T + 1), 256>>>(pooled2, W2, dW2, (long long)DD, part, D, D / SPLITS);

    // 12) final output
    final_out_kernel<<<(BATCH * D + TPB - 1) / TPB, TPB>>>(part, out);
}

// round 8
// speedup vs baseline: 7.2192x; 1.1732x over previous
#include <cuda_runtime.h>
#include <cuda_bf16.h>
#include <cstdint>

// ---------------- Problem constants ----------------
#define BATCH 64
#define NPATCH 196
#define D 768
#define T 8
#define HMETA 192
#define ROWS_TOT (BATCH * NPATCH)   // 12544
#define DD (D * D)
#define SPLITS 6
#define KC 64                        // K-chunk (bf16)
#define NKT 12                       // 768 / 64
#define ROWTILES1 98                 // 12544 / 128

// ---------------- Device scratch ----------------
__device__ __nv_bfloat16 g_patchesH[(size_t)(ROWS_TOT + 64) * D];   // 19.3 MB (+pad rows zero)
__device__ __nv_bfloat16 g_W1TH[DD];
__device__ __nv_bfloat16 g_dW1TH[(size_t)T * DD];
__device__ __nv_bfloat16 g_mixW1TH[(size_t)BATCH * DD];             // 75 MB
__device__ float g_pooled[BATCH * D];
__device__ float g_pooled2[BATCH * D];
__device__ float g_base[BATCH * D];
__device__ float g_hid[BATCH * HMETA];
__device__ float g_coefs[BATCH * T];
__device__ float g_nb1[BATCH * D];
__device__ float g_nb2[BATCH * D];
__device__ float g_part[(size_t)(T + 1) * SPLITS * BATCH * D];
__device__ float g_p1part[(size_t)ROWTILES1 * 2 * D];
__device__ float g_p2part[(size_t)BATCH * 2 * D];

// ---------------- PTX helpers (sm_80 baseline; ldmatrix is sm_75+) ----------------
__device__ __forceinline__ void cpasync16(uint32_t dst, const void* src) {
    asm volatile("cp.async.cg.shared.global [%0], [%1], 16;" :: "r"(dst), "l"(src));
}
__device__ __forceinline__ void cpasync_commit() {
    asm volatile("cp.async.commit_group;" ::: "memory");
}
__device__ __forceinline__ void mma_bf16(float* c, const uint32_t* a, const uint32_t* b) {
    asm volatile("mma.sync.aligned.m16n8k16.row.col.f32.bf16.bf16.f32 "
        "{%0,%1,%2,%3}, {%4,%5,%6,%7}, {%8,%9}, {%0,%1,%2,%3};"
        : "+f"(c[0]), "+f"(c[1]), "+f"(c[2]), "+f"(c[3])
        : "r"(a[0]), "r"(a[1]), "r"(a[2]), "r"(a[3]), "r"(b[0]), "r"(b[1]));
}
__device__ __forceinline__ void ldm_x4(uint32_t& r0, uint32_t& r1, uint32_t& r2, uint32_t& r3,
                                       uint32_t addr) {
    asm volatile("ldmatrix.sync.aligned.m8n8.x4.shared.b16 {%0,%1,%2,%3}, [%4];"
        : "=r"(r0), "=r"(r1), "=r"(r2), "=r"(r3) : "r"(addr));
}
__device__ __forceinline__ uint32_t packbf2(float lo, float hi) {
    __nv_bfloat162 p = __floats2bfloat162_rn(lo, hi);
    return *reinterpret_cast<uint32_t*>(&p);
}

// ---------------- SMEM layout for mma_gemm_pool ----------------
// 4 buffers of 128 x 72 halves (64 data + 8 pad). 144B row stride -> row-to-row
// bank offset 4; any 8 consecutive rows x 16B cover all 32 banks (conflict-free
// for both ldmatrix phases and the cp.async stores).
#define HSTRIDE 72
#define ROWB (HSTRIDE * 2)                // 144 bytes per row
#define STAGEH (128 * HSTRIDE)            // 9216 halves = 18432 bytes
#define SM_BYTES (4 * STAGEH * 2)         // 73728 bytes
#define SRED_OFF (128 * 132)              // float offset for reduction scratch

// load one 128x64 bf16 tile (row-major, ld = D halves) into smem [128][72]
__device__ __forceinline__ void load_tile64(__nv_bfloat16* dstBase,
                                            const __nv_bfloat16* src,
                                            int tid, int k0)
{
#pragma unroll
    for (int u = 0; u < 4; u++) {
        int q = tid + 256 * u;          // 0..1023
        int row = q >> 3;
        int c8 = (q & 7) * 8;           // halves
        uint32_t dst = (uint32_t)__cvta_generic_to_shared(dstBase + row * HSTRIDE + c8);
        cpasync16(dst, src + (size_t)row * D + k0 + c8);
    }
}

// ---------------- bf16 mma GEMM + fused relu + mean-pool partials ----------------
// D_tile = A[128xK] @ B_tile^T (B stored [N,K] K-major, bf16).
// Fragments loaded via ldmatrix.x4 (canonical cutlass lane mapping).
__global__ __launch_bounds__(256, 2)
void mma_gemm_pool(const __nv_bfloat16* __restrict__ A, const __nv_bfloat16* __restrict__ B,
                   const float* __restrict__ bias, float* __restrict__ part,
                   long long sA, long long sB, int biasPerZ,
                   int Mvalid, int rowIsGlobal)
{
    extern __shared__ __nv_bfloat16 smh[];
    __nv_bfloat16* bufA[2] = { smh,              smh + 2 * STAGEH };
    __nv_bfloat16* bufB[2] = { smh + STAGEH,     smh + 3 * STAGEH };

    int tid = threadIdx.x;
    int wid = tid >> 5;
    int lane = tid & 31;
    int q = lane >> 2;      // 0..7
    int t = lane & 3;       // 0..3
    int warpRow = (wid & 3) * 32;
    int warpCol = (wid >> 2) * 64;

    int rowBase = blockIdx.y * 128;
    int colBase = blockIdx.x * 128;
    long long z = blockIdx.z;
    const __nv_bfloat16* Arow = A + z * sA + (size_t)rowBase * D;
    const __nv_bfloat16* Brow = B + z * sB + (size_t)colBase * D;
    const float* biasp = bias + (biasPerZ ? z * (long long)D : 0) + colBase;

    // ldmatrix per-lane base offsets (bytes within a stage buffer)
    uint32_t smemU = (uint32_t)__cvta_generic_to_shared(smh);
    uint32_t bufAU[2] = { smemU,                 smemU + 2u * STAGEH * 2u };
    uint32_t bufBU[2] = { smemU + STAGEH * 2u,   smemU + 3u * STAGEH * 2u };
    // A: lanes 0-15 -> rows warpRow+mt*16+(lane&15) @ k-lo; lanes 16-31 same rows @ k+8
    uint32_t aOff = (uint32_t)((warpRow + (lane & 15)) * ROWB + ((lane >> 4) & 1) * 16);
    // B: lanes 0-7 nt0 rows @ k-lo; 8-15 nt0 @ k+8; 16-23 nt1 @ k-lo; 24-31 nt1 @ k+8
    uint32_t bOff = (uint32_t)((warpCol + (lane & 7) + ((lane & 16) ? 8 : 0)) * ROWB
                               + ((lane & 8) ? 16 : 0));

    float acc[2][8][4];
#pragma unroll
    for (int mt = 0; mt < 2; mt++)
#pragma unroll
        for (int nt = 0; nt < 8; nt++)
#pragma unroll
            for (int e = 0; e < 4; e++) acc[mt][nt][e] = 0.f;

    load_tile64(bufA[0], Arow, tid, 0);
    load_tile64(bufB[0], Brow, tid, 0);
    cpasync_commit();
    load_tile64(bufA[1], Arow, tid, KC);
    load_tile64(bufB[1], Brow, tid, KC);
    cpasync_commit();

    for (int kt = 0; kt < NKT; kt++) {
        int buf = kt & 1;
        if (kt < NKT - 2) asm volatile("cp.async.wait_group 1;" ::: "memory");
        else              asm volatile("cp.async.wait_group 0;" ::: "memory");
        __syncthreads();

        uint32_t aBase = bufAU[buf] + aOff;
        uint32_t bBase = bufBU[buf] + bOff;
#pragma unroll
        for (int ks = 0; ks < 4; ks++) {
            uint32_t a[2][4];
#pragma unroll
            for (int mt = 0; mt < 2; mt++)
                ldm_x4(a[mt][0], a[mt][1], a[mt][2], a[mt][3],
                       aBase + mt * (16 * ROWB) + ks * 32);
            uint32_t b[8][2];
#pragma unroll
            for (int p = 0; p < 4; p++) {
                uint32_t r0, r1, r2, r3;
                ldm_x4(r0, r1, r2, r3, bBase + p * (16 * ROWB) + ks * 32);
                b[2 * p][0] = r0; b[2 * p][1] = r1;
                b[2 * p + 1][0] = r2; b[2 * p + 1][1] = r3;
            }
#pragma unroll
            for (int mt = 0; mt < 2; mt++)
#pragma unroll
                for (int nt = 0; nt < 8; nt++)
                    mma_bf16(acc[mt][nt], a[mt], b[nt]);
        }
        __syncthreads();

        if (kt + 2 < NKT) {
            int k0 = (kt + 2) * KC;
            load_tile64(bufA[buf], Arow, tid, k0);
            load_tile64(bufB[buf], Brow, tid, k0);
            cpasync_commit();
        }
    }

    // ---- epilogue: stage relu(D+bias)/196 into smem (masked rows) ----
    float* sD = reinterpret_cast<float*>(smh);   // 128 x 132 fp32
    const float invR = 1.0f / (float)NPATCH;
#pragma unroll
    for (int mt = 0; mt < 2; mt++) {
        int r0 = warpRow + mt * 16 + q;
        int r1 = r0 + 8;
        bool v0 = (rowBase + r0) < Mvalid;
        bool v1 = (rowBase + r1) < Mvalid;
#pragma unroll
        for (int nt = 0; nt < 8; nt++) {
            int c = warpCol + nt * 8 + t * 2;
            float bv0 = biasp[c], bv1 = biasp[c + 1];
            float x0 = fmaxf(acc[mt][nt][0] + bv0, 0.f) * invR;
            float x1 = fmaxf(acc[mt][nt][1] + bv1, 0.f) * invR;
            float x2 = fmaxf(acc[mt][nt][2] + bv0, 0.f) * invR;
            float x3 = fmaxf(acc[mt][nt][3] + bv1, 0.f) * invR;
            sD[(size_t)r0 * 132 + c]     = v0 ? x0 : 0.f;
            sD[(size_t)r0 * 132 + c + 1] = v0 ? x1 : 0.f;
            sD[(size_t)r1 * 132 + c]     = v1 ? x2 : 0.f;
            sD[(size_t)r1 * 132 + c + 1] = v1 ? x3 : 0.f;
        }
    }
    __syncthreads();

    // ---- two-phase deterministic column reduction ----
    float* sRed = reinterpret_cast<float*>(smh) + SRED_OFF;
    {
        int col = tid & 127;
        int half = tid >> 7;
        int rbound = 128;
        if (rowIsGlobal) {
            int b0 = rowBase / NPATCH;
            rbound = (b0 + 1) * NPATCH - rowBase;
            if (rbound > 128) rbound = 128;
        }
        float a0 = 0.f, a1 = 0.f;
        int rs = half * 64;
        for (int r = rs; r < rs + 64; r++) {
            float v = sD[(size_t)r * 132 + col];
            if (r < rbound) a0 += v; else a1 += v;
        }
        sRed[(half * 2 + 0) * 128 + col] = a0;
        sRed[(half * 2 + 1) * 128 + col] = a1;
    }
    __syncthreads();
    if (tid < 128) {
        float s0 = sRed[0 * 128 + tid] + sRed[2 * 128 + tid];
        float s1 = sRed[1 * 128 + tid] + sRed[3 * 128 + tid];
        int col = colBase + tid;
        if (rowIsGlobal) {
            part[((size_t)blockIdx.y * 2 + 0) * D + col] = s0;
            part[((size_t)blockIdx.y * 2 + 1) * D + col] = s1;
        } else {
            part[((size_t)z * gridDim.y + blockIdx.y) * D + col] = s0;
        }
    }
}

// ---------------- combine pool partials ----------------
__global__ void combine1_kernel(const float* __restrict__ part, float* __restrict__ pooled)
{
    int idx = blockIdx.x * blockDim.x + threadIdx.x;
    if (idx >= BATCH * D) return;
    int j = idx % D;
    int b = idx / D;
    int r0 = (b * NPATCH) / 128;
    int r1 = (b * NPATCH + NPATCH - 1) / 128;
    float s = 0.f;
    for (int ry = r0; ry <= r1; ry++) {
        int tb = (ry * 128) / NPATCH;
        int slot = (b == tb) ? 0 : 1;
        s += part[((size_t)ry * 2 + slot) * D + j];
    }
    pooled[idx] = s;
}

__global__ void combine2_kernel(const float* __restrict__ part, float* __restrict__ pooled)
{
    int idx = blockIdx.x * blockDim.x + threadIdx.x;
    if (idx >= BATCH * D) return;
    int j = idx % D;
    int b = idx / D;
    pooled[idx] = part[((size_t)b * 2 + 0) * D + j] + part[((size_t)b * 2 + 1) * D + j];
}

// ---------------- patchify -> bf16 ----------------
__global__ void patchify4_kernel(const float* __restrict__ x, uint2* __restrict__ outH)
{
    int idx4 = blockIdx.x * blockDim.x + threadIdx.x;
    const int total4 = ROWS_TOT * (D / 4);
    if (idx4 >= total4) return;
    int d4 = idx4 % (D / 4);
    int rem = idx4 / (D / 4);
    int n = rem % NPATCH;
    int b = rem / NPATCH;
    int d = d4 * 4;
    int c = d >> 8;
    int r2 = d & 255;
    int i = r2 >> 4;
    int j = r2 & 15;
    int hp = n / 14;
    int wp = n % 14;
    int src = ((b * 3 + c) * 224 + hp * 16 + i) * 224 + wp * 16 + j;
    float4 v = *reinterpret_cast<const float4*>(x + src);
    uint2 o;
    o.x = packbf2(v.x, v.y);
    o.y = packbf2(v.z, v.w);
    outH[idx4] = o;
}

// ---------------- transpose W1 / dW1 -> [N,K] bf16 ----------------
__global__ void transpose_kernel(const float* __restrict__ W1, const float* __restrict__ dW1,
                                 __nv_bfloat16* __restrict__ W1TH,
                                 __nv_bfloat16* __restrict__ dW1TH)
{
    __shared__ float tile[32][33];
    int z = blockIdx.z;
    const float* src = (z == 0) ? W1 : dW1 + (size_t)(z - 1) * DD;
    __nv_bfloat16* dst = (z == 0) ? W1TH : dW1TH + (size_t)(z - 1) * DD;
    int xx = blockIdx.x * 32 + threadIdx.x;
    int y0 = blockIdx.y * 32;
    for (int i = threadIdx.y; i < 32; i += 8)
        tile[i][threadIdx.x] = src[(size_t)(y0 + i) * D + xx];
    __syncthreads();
    int ox = blockIdx.y * 32 + threadIdx.x;
    int oy0 = blockIdx.x * 32;
    for (int i = threadIdx.y; i < 32; i += 8)
        dst[(size_t)(oy0 + i) * D + ox] = __float2bfloat16_rn(tile[threadIdx.x][i]);
}

// ---------------- Small GEMM (M=64, fp32) with split-K partials ----------------
#define SBK 32
__global__ __launch_bounds__(256)
void small_gemm(const float* __restrict__ A, const float* __restrict__ B0,
                const float* __restrict__ Bd, long long sB,
                float* __restrict__ part, int N, int Kc)
{
    int z = blockIdx.z;
    const float* B;
    if (B0) B = (z == 0) ? B0 : (Bd + (long long)(z - 1) * sB);
    else    B = Bd + (long long)z * sB;

    int S = gridDim.y;
    int sy = blockIdx.y;
    int colBase = blockIdx.x * 64;
    int k0 = sy * Kc;

    __shared__ float As[SBK][64];
    __shared__ float Bs[SBK][64];

    int tid = threadIdx.x;
    int tx = tid & 15;
    int ty = tid >> 4;

    float acc[4][4];
#pragma unroll
    for (int i = 0; i < 4; i++)
#pragma unroll
        for (int j = 0; j < 4; j++) acc[i][j] = 0.f;

    for (int kb = 0; kb < Kc; kb += SBK) {
#pragma unroll
        for (int u = 0; u < 2; u++) {
            int qq = tid + 256 * u;
            int row = qq >> 3;
            int kq = (qq & 7) * 4;
            float4 av = *reinterpret_cast<const float4*>(A + (long long)row * D + k0 + kb + kq);
            As[kq + 0][row] = av.x;
            As[kq + 1][row] = av.y;
            As[kq + 2][row] = av.z;
            As[kq + 3][row] = av.w;
        }
#pragma unroll
        for (int u = 0; u < 2; u++) {
            int qq = tid + 256 * u;
            int k = qq >> 4;
            int col4 = (qq & 15) * 4;
            *reinterpret_cast<float4*>(&Bs[k][col4]) =
                *reinterpret_cast<const float4*>(B + (long long)(k0 + kb + k) * N + colBase + col4);
        }
        __syncthreads();
#pragma unroll
        for (int k = 0; k < SBK; k++) {
            float4 a4 = *reinterpret_cast<const float4*>(&As[k][ty * 4]);
            float4 b4 = *reinterpret_cast<const float4*>(&Bs[k][tx * 4]);
            float ra[4] = {a4.x, a4.y, a4.z, a4.w};
            float rb[4] = {b4.x, b4.y, b4.z, b4.w};
#pragma unroll
            for (int i = 0; i < 4; i++)
#pragma unroll
                for (int j = 0; j < 4; j++)
                    acc[i][j] = fmaf(ra[i], rb[j], acc[i][j]);
        }
        __syncthreads();
    }

    float* dst = part + ((long long)(z * S + sy) * 64) * N;
#pragma unroll
    for (int i = 0; i < 4; i++) {
        int r = ty * 4 + i;
        *reinterpret_cast<float4*>(dst + (long long)r * N + colBase + tx * 4) =
            make_float4(acc[i][0], acc[i][1], acc[i][2], acc[i][3]);
    }
}

__global__ void reduce_kernel(const float* __restrict__ part, float* __restrict__ dst,
                              const float* __restrict__ bias, int N, int relu)
{
    int idx = blockIdx.x * blockDim.x + threadIdx.x;
    if (idx >= BATCH * N) return;
    float v = bias ? bias[idx % N] : 0.f;
#pragma unroll
    for (int s = 0; s < SPLITS; s++) v += part[(long long)s * BATCH * N + idx];
    if (relu) v = fmaxf(v, 0.f);
    dst[idx] = v;
}

__global__ void coefs_kernel(const float* __restrict__ mw2, const float* __restrict__ mb2)
{
    int t = threadIdx.x;
    int b = t >> 3;
    int j = t & 7;
    float s = mb2[j];
    for (int k = 0; k < HMETA; k++)
        s = fmaf(g_hid[b * HMETA + k], mw2[k * T + j], s);
    g_coefs[b * T + j] = s;
}

__global__ void mixbias_kernel(const float* __restrict__ b1, const float* __restrict__ db1,
                               const float* __restrict__ b2, const float* __restrict__ db2)
{
    int idx = blockIdx.x * blockDim.x + threadIdx.x;
    if (idx >= BATCH * D) return;
    int j = idx % D;
    int b = idx / D;
    float c[T];
#pragma unroll
    for (int t = 0; t < T; t++) c[t] = g_coefs[b * T + t];
    float v1 = b1[j], v2 = b2[j];
#pragma unroll
    for (int t = 0; t < T; t++) {
        v1 = fmaf(c[t], db1[t * D + j], v1);
        v2 = fmaf(c[t], db2[t * D + j], v2);
    }
    g_nb1[idx] = v1;
    g_nb2[idx] = v2;
}

// ---------------- mixW1TH: batch-in-registers, bf16 in/out ----------------
__global__ __launch_bounds__(256)
void mixw1t_kernel(void)
{
    __shared__ float sc[BATCH * T];
    int tid = threadIdx.x;
    reinterpret_cast<float2*>(sc)[tid] = reinterpret_cast<const float2*>(g_coefs)[tid];
    __syncthreads();

    const long long per_b4 = DD / 4;                         // uint2 positions per batch
    long long r = (long long)blockIdx.x * 256 + tid;

    const __nv_bfloat162* w2p = reinterpret_cast<const __nv_bfloat162*>(g_W1TH);
    float w[4];
    {
        float2 lo = __bfloat1622float2(w2p[2 * r]);
        float2 hi = __bfloat1622float2(w2p[2 * r + 1]);
        w[0] = lo.x; w[1] = lo.y; w[2] = hi.x; w[3] = hi.y;
    }
    float dv[T][4];
#pragma unroll
    for (int t = 0; t < T; t++) {
        const __nv_bfloat162* dp =
            reinterpret_cast<const __nv_bfloat162*>(g_dW1TH + (size_t)t * DD);
        float2 lo = __bfloat1622float2(dp[2 * r]);
        float2 hi = __bfloat1622float2(dp[2 * r + 1]);
        dv[t][0] = lo.x; dv[t][1] = lo.y; dv[t][2] = hi.x; dv[t][3] = hi.y;
    }

    uint2* outp = reinterpret_cast<uint2*>(g_mixW1TH) + r;
#pragma unroll 4
    for (int b = 0; b < BATCH; b++) {
        float v0 = w[0], v1 = w[1], v2 = w[2], v3 = w[3];
#pragma unroll
        for (int t = 0; t < T; t++) {
            float c = sc[b * T + t];
            v0 = fmaf(c, dv[t][0], v0);
            v1 = fmaf(c, dv[t][1], v1);
            v2 = fmaf(c, dv[t][2], v2);
            v3 = fmaf(c, dv[t][3], v3);
        }
        uint2 o;
        o.x = packbf2(v0, v1);
        o.y = packbf2(v2, v3);
        outp[(long long)b * per_b4] = o;
    }
}

__global__ void final_out_kernel(const float* __restrict__ part, float* __restrict__ out)
{
    int idx = blockIdx.x * blockDim.x + threadIdx.x;
    if (idx >= BATCH * D) return;
    int b = idx / D;
    const int SLAB = BATCH * D;
    float v = g_nb2[idx];
#pragma unroll
    for (int s = 0; s < SPLITS; s++) v += part[(long long)s * SLAB + idx];
#pragma unroll
    for (int t = 0; t < T; t++) {
        float qv = 0.f;
#pragma unroll
        for (int s = 0; s < SPLITS; s++)
            qv += part[(long long)((t + 1) * SPLITS + s) * SLAB + idx];
        v = fmaf(g_coefs[b * T + t], qv, v);
    }
    out[idx] = v;
}

// ---------------- launch ----------------
extern "C" void kernel_launch(void* const* d_in, const int* in_sizes, int n_in,
                              void* d_out, int out_size)
{
    const float* x   = (const float*)d_in[0];
    const float* W1  = (const float*)d_in[1];
    const float* b1  = (const float*)d_in[2];
    const float* W2  = (const float*)d_in[3];
    const float* b2  = (const float*)d_in[4];
    const float* dW1 = (const float*)d_in[5];
    const float* db1 = (const float*)d_in[6];
    const float* dW2 = (const float*)d_in[7];
    const float* db2 = (const float*)d_in[8];
    const float* mw1 = (const float*)d_in[9];
    const float* mb1 = (const float*)d_in[10];
    const float* mw2 = (const float*)d_in[11];
    const float* mb2 = (const float*)d_in[12];
    float* out = (float*)d_out;

    __nv_bfloat16 *patchesH, *W1TH, *dW1TH, *mixW1TH;
    float *pooled, *pooled2, *base, *hid, *part, *p1part, *p2part, *nb1;
    cudaGetSymbolAddress((void**)&patchesH, g_patchesH);
    cudaGetSymbolAddress((void**)&W1TH,     g_W1TH);
    cudaGetSymbolAddress((void**)&dW1TH,    g_dW1TH);
    cudaGetSymbolAddress((void**)&mixW1TH,  g_mixW1TH);
    cudaGetSymbolAddress((void**)&pooled,   g_pooled);
    cudaGetSymbolAddress((void**)&pooled2,  g_pooled2);
    cudaGetSymbolAddress((void**)&base,     g_base);
    cudaGetSymbolAddress((void**)&hid,      g_hid);
    cudaGetSymbolAddress((void**)&part,     g_part);
    cudaGetSymbolAddress((void**)&p1part,   g_p1part);
    cudaGetSymbolAddress((void**)&p2part,   g_p2part);
    cudaGetSymbolAddress((void**)&nb1,      g_nb1);

    cudaFuncSetAttribute(mma_gemm_pool, cudaFuncAttributeMaxDynamicSharedMemorySize, SM_BYTES);

    const int TPB = 256;

    // 1) patchify -> bf16
    {
        int total4 = ROWS_TOT * (D / 4);
        patchify4_kernel<<<(total4 + TPB - 1) / TPB, TPB>>>(x, (uint2*)patchesH);
    }

    // 2) transpose W1 -> W1TH, dW1 -> dW1TH (bf16)
    transpose_kernel<<<dim3(D / 32, D / 32, T + 1), dim3(32, 8)>>>(W1, dW1, W1TH, dW1TH);

    // 3) GEMM1 (bf16 mma + ldmatrix) fused relu+pool partials
    mma_gemm_pool<<<dim3(D / 128, ROWTILES1, 1), 256, SM_BYTES>>>(
        patchesH, W1TH, b1, p1part, 0, 0, 0, ROWS_TOT, 1);
    combine1_kernel<<<(BATCH * D + TPB - 1) / TPB, TPB>>>(p1part, pooled);

    // 4) base = pooled @ W2 + b2
    small_gemm<<<dim3(D / 64, SPLITS, 1), 256>>>(pooled, W2, nullptr, 0, part, D, D / SPLITS);
    reduce_kernel<<<(BATCH * D + TPB - 1) / TPB, TPB>>>(part, base, b2, D, 0);

    // 5) hid = relu(base @ mw1 + mb1)
    small_gemm<<<dim3(HMETA / 64, SPLITS, 1), 256>>>(base, mw1, nullptr, 0, part, HMETA, D / SPLITS);
    reduce_kernel<<<(BATCH * HMETA + TPB - 1) / TPB, TPB>>>(part, hid, mb1, HMETA, 1);

    // 6) coefs
    coefs_kernel<<<1, 512>>>(mw2, mb2);

    // 7) mixed biases
    mixbias_kernel<<<(BATCH * D + TPB - 1) / TPB, TPB>>>(b1, db1, b2, db2);

    // 8) mixW1TH (batch-in-registers, bf16)
    mixw1t_kernel<<<DD / 4 / 256, 256>>>();

    // 9) GEMM2 (bf16 mma + ldmatrix, batched) fused relu+pool partials
    mma_gemm_pool<<<dim3(D / 128, 2, BATCH), 256, SM_BYTES>>>(
        patchesH, mixW1TH, nb1, p2part,
        (long long)NPATCH * D, (long long)DD, 1, NPATCH, 0);
    combine2_kernel<<<(BATCH * D + TPB - 1) / TPB, TPB>>>(p2part, pooled2);

    // 10+11) q (dW2 tasks) + W2 head via z=0 (split-K partials)
    small_gemm<<<dim3(D / 64, SPLITS, T + 1), 256>>>(pooled2, W2, dW2, (long long)DD, part, D, D / SPLITS);

    // 12) final output
    final_out_kernel<<<(BATCH * D + TPB - 1) / TPB, TPB>>>(part, out);
}